// round 4
// baseline (speedup 1.0000x reference)
#include <cuda_runtime.h>
#include <math.h>
#include <stdint.h>

// Problem constants
#define BSZ   4
#define NQ    2048
#define MK    2048
#define DIMX  1024
#define CTXD  1024
#define HEADS 8
#define DHEAD 64
#define INNER 512   // HEADS * DHEAD

// Scratch (allocation-free rule: __device__ globals)
__device__ float g_Q[(size_t)BSZ * NQ * INNER];
__device__ float g_K[(size_t)BSZ * MK * INNER];
__device__ float g_V[(size_t)BSZ * MK * INNER];
__device__ float g_O[(size_t)BSZ * NQ * INNER];

// ----------------------------------------------------------------------------
// 3xTF32 helpers
// ----------------------------------------------------------------------------
__device__ __forceinline__ uint32_t f2tf(float x) {
    uint32_t u;
    asm("cvt.rna.tf32.f32 %0, %1;" : "=r"(u) : "f"(x));
    return u;
}
__device__ __forceinline__ void split_tf32(float x, uint32_t& h, uint32_t& l) {
    h = f2tf(x);
    l = f2tf(x - __uint_as_float(h));
}
__device__ __forceinline__ void mma8(float c[4], const uint32_t a[4], const uint32_t b[2]) {
    asm volatile(
        "mma.sync.aligned.m16n8k8.row.col.f32.tf32.tf32.f32 "
        "{%0,%1,%2,%3},{%4,%5,%6,%7},{%8,%9},{%0,%1,%2,%3};"
        : "+f"(c[0]), "+f"(c[1]), "+f"(c[2]), "+f"(c[3])
        : "r"(a[0]), "r"(a[1]), "r"(a[2]), "r"(a[3]), "r"(b[0]), "r"(b[1]));
}
__device__ __forceinline__ void mma_x3(float c[4],
                                       const uint32_t ah[4], const uint32_t al[4],
                                       const uint32_t bh[2], const uint32_t bl[2]) {
    mma8(c, ah, bh);
    mma8(c, ah, bl);
    mma8(c, al, bh);
}

// ----------------------------------------------------------------------------
// Tensor-core GEMM: C[M,N] = A[M,K] @ W[K,N] (+bias), 3xTF32, pre-split smem.
// BM=128, BN=64, BK=32. 256 threads = 8 warps (4m x 2n), warp tile 32x32.
// Dynamic smem: Ah/Al [32][132], Bh/Bl [32][68] (tf32-rounded floats).
// ----------------------------------------------------------------------------
#define ASTR 132
#define BSTR 68
#define GEMM_SMEM_BYTES ((2 * 32 * ASTR + 2 * 32 * BSTR) * (int)sizeof(float))

__global__ __launch_bounds__(256)
void gemm_tc(const float* __restrict__ A, const float* __restrict__ W,
             float* __restrict__ C, const float* __restrict__ bias,
             int M, int N, int K)
{
    extern __shared__ float gsm[];
    float* Ah = gsm;
    float* Al = Ah + 32 * ASTR;
    float* Bh = Al + 32 * ASTR;
    float* Bl = Bh + 32 * BSTR;

    const int tid = threadIdx.x;
    const int lane = tid & 31, warp = tid >> 5;
    const int wm = warp & 3, wn = warp >> 2;
    const int g = lane >> 2, t = lane & 3;
    const int m0 = blockIdx.y * 128, n0 = blockIdx.x * 64;

    // staging maps: A row per thread-pair (16 k each), B row per 8 threads
    const int lm = tid >> 1, lk = (tid & 1) * 16;
    const int bkr = tid >> 3, bn = (tid & 7) * 8;

    float acc[2][4][4];
    #pragma unroll
    for (int mt = 0; mt < 2; mt++)
        #pragma unroll
        for (int nt = 0; nt < 4; nt++)
            #pragma unroll
            for (int i = 0; i < 4; i++) acc[mt][nt][i] = 0.f;

    for (int k0 = 0; k0 < K; k0 += 32) {
        // stage + split A [128 m][32 k] -> Ah/Al [k][m]
        const float* ap = A + (size_t)(m0 + lm) * K + k0 + lk;
        #pragma unroll
        for (int jj = 0; jj < 4; jj++) {
            float4 a = *(const float4*)(ap + jj * 4);
            float va[4] = {a.x, a.y, a.z, a.w};
            #pragma unroll
            for (int e = 0; e < 4; e++) {
                uint32_t h, l;
                split_tf32(va[e], h, l);
                Ah[(lk + jj * 4 + e) * ASTR + lm] = __uint_as_float(h);
                Al[(lk + jj * 4 + e) * ASTR + lm] = __uint_as_float(l);
            }
        }
        // stage + split B [32 k][64 n]
        const float* bp = W + (size_t)(k0 + bkr) * N + n0 + bn;
        #pragma unroll
        for (int jj = 0; jj < 2; jj++) {
            float4 b = *(const float4*)(bp + jj * 4);
            float vb[4] = {b.x, b.y, b.z, b.w};
            #pragma unroll
            for (int e = 0; e < 4; e++) {
                uint32_t h, l;
                split_tf32(vb[e], h, l);
                Bh[bkr * BSTR + bn + jj * 4 + e] = __uint_as_float(h);
                Bl[bkr * BSTR + bn + jj * 4 + e] = __uint_as_float(l);
            }
        }
        __syncthreads();

        #pragma unroll
        for (int s = 0; s < 32; s += 8) {
            uint32_t ah[2][4], al[2][4];
            #pragma unroll
            for (int mt = 0; mt < 2; mt++) {
                const int mr = wm * 32 + mt * 16;
                ah[mt][0] = __float_as_uint(Ah[(s + t    ) * ASTR + mr + g    ]);
                ah[mt][1] = __float_as_uint(Ah[(s + t    ) * ASTR + mr + g + 8]);
                ah[mt][2] = __float_as_uint(Ah[(s + t + 4) * ASTR + mr + g    ]);
                ah[mt][3] = __float_as_uint(Ah[(s + t + 4) * ASTR + mr + g + 8]);
                al[mt][0] = __float_as_uint(Al[(s + t    ) * ASTR + mr + g    ]);
                al[mt][1] = __float_as_uint(Al[(s + t    ) * ASTR + mr + g + 8]);
                al[mt][2] = __float_as_uint(Al[(s + t + 4) * ASTR + mr + g    ]);
                al[mt][3] = __float_as_uint(Al[(s + t + 4) * ASTR + mr + g + 8]);
            }
            #pragma unroll
            for (int nt = 0; nt < 4; nt++) {
                const int nc = wn * 32 + nt * 8 + g;
                uint32_t bh[2], bl[2];
                bh[0] = __float_as_uint(Bh[(s + t    ) * BSTR + nc]);
                bh[1] = __float_as_uint(Bh[(s + t + 4) * BSTR + nc]);
                bl[0] = __float_as_uint(Bl[(s + t    ) * BSTR + nc]);
                bl[1] = __float_as_uint(Bl[(s + t + 4) * BSTR + nc]);
                mma_x3(acc[0][nt], ah[0], al[0], bh, bl);
                mma_x3(acc[1][nt], ah[1], al[1], bh, bl);
            }
        }
        __syncthreads();
    }

    #pragma unroll
    for (int mt = 0; mt < 2; mt++) {
        const int r0 = m0 + wm * 32 + mt * 16 + g;
        #pragma unroll
        for (int nt = 0; nt < 4; nt++) {
            const int c0 = n0 + wn * 32 + nt * 8 + t * 2;
            float2 v0 = make_float2(acc[mt][nt][0], acc[mt][nt][1]);
            float2 v1 = make_float2(acc[mt][nt][2], acc[mt][nt][3]);
            if (bias) {
                float b0v = bias[c0], b1v = bias[c0 + 1];
                v0.x += b0v; v0.y += b1v;
                v1.x += b0v; v1.y += b1v;
            }
            *(float2*)(C + (size_t)r0 * N + c0) = v0;
            *(float2*)(C + (size_t)(r0 + 8) * N + c0) = v1;
        }
    }
}

// ----------------------------------------------------------------------------
// Tensor-core flash attention. QK^T = 3xTF32 (K pre-split in smem, Q split
// inline). P@V = 2xTF32 (V pre-split, P stored tf32-rounded -> single pass).
// Per CTA: 64 queries, one (b,h). 128 threads, warp owns 16 q-rows.
// Dynamic smem: Qs[64][68] raw, Kh/Kl[64][68] (reused for Vh/Vl),
// Ps[64][68] (tf32 P), msk[64].
// ----------------------------------------------------------------------------
#define FSTR 68
#define FLASH_SMEM_BYTES ((4 * 64 * FSTR + 64) * (int)sizeof(float))

__global__ __launch_bounds__(128)
void flash_tc(const float* __restrict__ Q, const float* __restrict__ K,
              const float* __restrict__ V, const int* __restrict__ mask,
              float* __restrict__ O)
{
    extern __shared__ float sm[];
    float (*Qs)[FSTR] = (float (*)[FSTR])sm;                    // raw fp32 Q
    float (*Kh)[FSTR] = (float (*)[FSTR])(sm + 64 * FSTR);      // K hi / V hi
    float (*Kl)[FSTR] = (float (*)[FSTR])(sm + 2 * 64 * FSTR);  // K lo / V lo
    float (*Ps)[FSTR] = (float (*)[FSTR])(sm + 3 * 64 * FSTR);  // tf32 P
    float* msk = sm + 4 * 64 * FSTR;

    const int bh = blockIdx.y;
    const int b = bh >> 3, h = bh & 7;
    const int q0 = blockIdx.x * 64;

    const int tid = threadIdx.x;
    const int lane = tid & 31, warp = tid >> 5;
    const int g = lane >> 2, t = lane & 3;
    const int pr = warp * 16;

    const float* Qb = Q + (size_t)b * NQ * INNER + (size_t)h * DHEAD;
    const float* Kb = K + (size_t)b * MK * INNER + (size_t)h * DHEAD;
    const float* Vb = V + (size_t)b * MK * INNER + (size_t)h * DHEAD;
    const int* mb = mask + (size_t)b * MK;

    // stage Q tile [64 q][64 d] (raw)
    for (int i = tid; i < 64 * 16; i += 128) {
        int r = i >> 4, c = (i & 15) * 4;
        *(float4*)&Qs[r][c] = *(const float4*)(Qb + (size_t)(q0 + r) * INNER + c);
    }

    float of[8][4];
    #pragma unroll
    for (int nt = 0; nt < 8; nt++)
        #pragma unroll
        for (int i = 0; i < 4; i++) of[nt][i] = 0.f;
    float mrow0 = -3.0e38f, mrow1 = -3.0e38f, lrow0 = 0.f, lrow1 = 0.f;
    const float scale = 0.125f;

    for (int kt = 0; kt < MK; kt += 64) {
        __syncthreads();   // prev PV done with Kh/Kl and Ps; Qs staged (iter 0)
        // stage + split K tile
        for (int i = tid; i < 64 * 16; i += 128) {
            int r = i >> 4, c = (i & 15) * 4;
            float4 v = *(const float4*)(Kb + (size_t)(kt + r) * INNER + c);
            float va[4] = {v.x, v.y, v.z, v.w};
            #pragma unroll
            for (int e = 0; e < 4; e++) {
                uint32_t hh, ll;
                split_tf32(va[e], hh, ll);
                Kh[r][c + e] = __uint_as_float(hh);
                Kl[r][c + e] = __uint_as_float(ll);
            }
        }
        if (tid < 64) msk[tid] = (mb[kt + tid] != 0) ? 0.f : -1.0e30f;
        __syncthreads();

        // ---- S = Q K^T (3xTF32) ----
        float sf[8][4];
        #pragma unroll
        for (int nt = 0; nt < 8; nt++)
            #pragma unroll
            for (int i = 0; i < 4; i++) sf[nt][i] = 0.f;

        #pragma unroll
        for (int s = 0; s < 64; s += 8) {
            uint32_t ah[4], al[4];
            split_tf32(Qs[pr + g    ][s + t    ], ah[0], al[0]);
            split_tf32(Qs[pr + g + 8][s + t    ], ah[1], al[1]);
            split_tf32(Qs[pr + g    ][s + t + 4], ah[2], al[2]);
            split_tf32(Qs[pr + g + 8][s + t + 4], ah[3], al[3]);
            #pragma unroll
            for (int nt = 0; nt < 8; nt++) {
                uint32_t bh2[2], bl2[2];
                bh2[0] = __float_as_uint(Kh[nt * 8 + g][s + t    ]);
                bh2[1] = __float_as_uint(Kh[nt * 8 + g][s + t + 4]);
                bl2[0] = __float_as_uint(Kl[nt * 8 + g][s + t    ]);
                bl2[1] = __float_as_uint(Kl[nt * 8 + g][s + t + 4]);
                mma_x3(sf[nt], ah, al, bh2, bl2);
            }
        }

        // ---- scale + mask + online softmax ----
        float mx0 = -3.0e38f, mx1 = -3.0e38f;
        #pragma unroll
        for (int nt = 0; nt < 8; nt++) {
            float mk0 = msk[nt * 8 + 2 * t], mk1 = msk[nt * 8 + 2 * t + 1];
            sf[nt][0] = sf[nt][0] * scale + mk0;
            sf[nt][1] = sf[nt][1] * scale + mk1;
            sf[nt][2] = sf[nt][2] * scale + mk0;
            sf[nt][3] = sf[nt][3] * scale + mk1;
            mx0 = fmaxf(mx0, fmaxf(sf[nt][0], sf[nt][1]));
            mx1 = fmaxf(mx1, fmaxf(sf[nt][2], sf[nt][3]));
        }
        mx0 = fmaxf(mx0, __shfl_xor_sync(0xffffffffu, mx0, 1));
        mx0 = fmaxf(mx0, __shfl_xor_sync(0xffffffffu, mx0, 2));
        mx1 = fmaxf(mx1, __shfl_xor_sync(0xffffffffu, mx1, 1));
        mx1 = fmaxf(mx1, __shfl_xor_sync(0xffffffffu, mx1, 2));

        const float mn0 = fmaxf(mrow0, mx0), mn1 = fmaxf(mrow1, mx1);
        const float corr0 = __expf(mrow0 - mn0), corr1 = __expf(mrow1 - mn1);
        float ls0 = 0.f, ls1 = 0.f;
        #pragma unroll
        for (int nt = 0; nt < 8; nt++) {
            sf[nt][0] = __expf(sf[nt][0] - mn0);
            sf[nt][1] = __expf(sf[nt][1] - mn0);
            sf[nt][2] = __expf(sf[nt][2] - mn1);
            sf[nt][3] = __expf(sf[nt][3] - mn1);
            ls0 += sf[nt][0] + sf[nt][1];
            ls1 += sf[nt][2] + sf[nt][3];
        }
        ls0 += __shfl_xor_sync(0xffffffffu, ls0, 1);
        ls0 += __shfl_xor_sync(0xffffffffu, ls0, 2);
        ls1 += __shfl_xor_sync(0xffffffffu, ls1, 1);
        ls1 += __shfl_xor_sync(0xffffffffu, ls1, 2);

        lrow0 = lrow0 * corr0 + ls0; mrow0 = mn0;
        lrow1 = lrow1 * corr1 + ls1; mrow1 = mn1;

        #pragma unroll
        for (int nt = 0; nt < 8; nt++) {
            of[nt][0] *= corr0; of[nt][1] *= corr0;
            of[nt][2] *= corr1; of[nt][3] *= corr1;
        }

        // write tf32-rounded P (own rows)
        #pragma unroll
        for (int nt = 0; nt < 8; nt++) {
            Ps[pr + g    ][nt * 8 + 2 * t    ] = __uint_as_float(f2tf(sf[nt][0]));
            Ps[pr + g    ][nt * 8 + 2 * t + 1] = __uint_as_float(f2tf(sf[nt][1]));
            Ps[pr + g + 8][nt * 8 + 2 * t    ] = __uint_as_float(f2tf(sf[nt][2]));
            Ps[pr + g + 8][nt * 8 + 2 * t + 1] = __uint_as_float(f2tf(sf[nt][3]));
        }

        __syncthreads();   // all warps done reading K
        // stage + split V tile (reuse Kh/Kl)
        for (int i = tid; i < 64 * 16; i += 128) {
            int r = i >> 4, c = (i & 15) * 4;
            float4 v = *(const float4*)(Vb + (size_t)(kt + r) * INNER + c);
            float va[4] = {v.x, v.y, v.z, v.w};
            #pragma unroll
            for (int e = 0; e < 4; e++) {
                uint32_t hh, ll;
                split_tf32(va[e], hh, ll);
                Kh[r][c + e] = __uint_as_float(hh);
                Kl[r][c + e] = __uint_as_float(ll);
            }
        }
        __syncthreads();   // V staged + Ps visible

        // ---- O += P @ V (2xTF32: P single, V split) ----
        #pragma unroll
        for (int s = 0; s < 64; s += 8) {
            uint32_t pa[4];
            pa[0] = __float_as_uint(Ps[pr + g    ][s + t    ]);
            pa[1] = __float_as_uint(Ps[pr + g + 8][s + t    ]);
            pa[2] = __float_as_uint(Ps[pr + g    ][s + t + 4]);
            pa[3] = __float_as_uint(Ps[pr + g + 8][s + t + 4]);
            #pragma unroll
            for (int nt = 0; nt < 8; nt++) {
                uint32_t bh2[2], bl2[2];
                bh2[0] = __float_as_uint(Kh[s + t    ][nt * 8 + g]);
                bh2[1] = __float_as_uint(Kh[s + t + 4][nt * 8 + g]);
                bl2[0] = __float_as_uint(Kl[s + t    ][nt * 8 + g]);
                bl2[1] = __float_as_uint(Kl[s + t + 4][nt * 8 + g]);
                mma8(of[nt], pa, bh2);
                mma8(of[nt], pa, bl2);
            }
        }
    }

    // epilogue
    const float inv0 = 1.f / lrow0, inv1 = 1.f / lrow1;
    const int qa = q0 + pr + g;
    #pragma unroll
    for (int nt = 0; nt < 8; nt++) {
        const int col = h * DHEAD + nt * 8 + 2 * t;
        float2 v0 = make_float2(of[nt][0] * inv0, of[nt][1] * inv0);
        float2 v1 = make_float2(of[nt][2] * inv1, of[nt][3] * inv1);
        *(float2*)(O + (size_t)(b * NQ + qa) * INNER + col) = v0;
        *(float2*)(O + (size_t)(b * NQ + qa + 8) * INNER + col) = v1;
    }
}

// ----------------------------------------------------------------------------
// kernel_launch
// ----------------------------------------------------------------------------
extern "C" void kernel_launch(void* const* d_in, const int* in_sizes, int n_in,
                              void* d_out, int out_size)
{
    const float* x    = (const float*)d_in[0];
    const float* ctx  = (const float*)d_in[1];
    const int*   mask = (const int*)d_in[2];
    const float* Wq   = (const float*)d_in[3];
    const float* Wk   = (const float*)d_in[4];
    const float* Wv   = (const float*)d_in[5];
    const float* Wo   = (const float*)d_in[6];
    const float* bo   = (const float*)d_in[7];
    float* out = (float*)d_out;

    float *pQ, *pK, *pV, *pO;
    cudaGetSymbolAddress((void**)&pQ, g_Q);
    cudaGetSymbolAddress((void**)&pK, g_K);
    cudaGetSymbolAddress((void**)&pV, g_V);
    cudaGetSymbolAddress((void**)&pO, g_O);

    const int rowsX = BSZ * NQ;   // 8192
    const int rowsC = BSZ * MK;   // 8192

    cudaFuncSetAttribute(gemm_tc, cudaFuncAttributeMaxDynamicSharedMemorySize,
                         GEMM_SMEM_BYTES);
    cudaFuncSetAttribute(flash_tc, cudaFuncAttributeMaxDynamicSharedMemorySize,
                         FLASH_SMEM_BYTES);

    {   // projections
        dim3 gq(INNER / 64, rowsX / 128);
        gemm_tc<<<gq, 256, GEMM_SMEM_BYTES>>>(x, Wq, pQ, nullptr, rowsX, INNER, DIMX);
        dim3 gk(INNER / 64, rowsC / 128);
        gemm_tc<<<gk, 256, GEMM_SMEM_BYTES>>>(ctx, Wk, pK, nullptr, rowsC, INNER, CTXD);
        gemm_tc<<<gk, 256, GEMM_SMEM_BYTES>>>(ctx, Wv, pV, nullptr, rowsC, INNER, CTXD);
    }
    {   // flash attention
        dim3 grid(NQ / 64, BSZ * HEADS);
        flash_tc<<<grid, 128, FLASH_SMEM_BYTES>>>(pQ, pK, pV, mask, pO);
    }
    {   // out = O @ Wo + bo
        dim3 go(DIMX / 64, rowsX / 128);
        gemm_tc<<<go, 256, GEMM_SMEM_BYTES>>>(pO, Wo, out, bo, rowsX, DIMX, INNER);
    }
}

// round 6
// speedup vs baseline: 1.7029x; 1.7029x over previous
#include <cuda_runtime.h>
#include <math.h>
#include <stdint.h>

// Problem constants
#define BSZ   4
#define NQ    2048
#define MK    2048
#define DIMX  1024
#define CTXD  1024
#define HEADS 8
#define DHEAD 64
#define INNER 512   // HEADS * DHEAD

// Scratch (allocation-free rule: __device__ globals)
__device__ float g_Q[(size_t)BSZ * NQ * INNER];
__device__ float g_K[(size_t)BSZ * MK * INNER];
__device__ float g_V[(size_t)BSZ * MK * INNER];
__device__ float g_O[(size_t)BSZ * NQ * INNER];

// ----------------------------------------------------------------------------
// bf16 x3 helpers. Pack (e0,e1) -> bf16x2 word with e0 in low 16 bits.
// split: hi = bf16(x) (rn), lo = bf16(x - hi). a*b ~= ah*bh + ah*bl + al*bh,
// per-product rel error ~2^-17.
// ----------------------------------------------------------------------------
__device__ __forceinline__ uint32_t pack_bf16x2(float e0, float e1) {
    uint32_t r;
    asm("cvt.rn.bf16x2.f32 %0, %1, %2;" : "=r"(r) : "f"(e1), "f"(e0));
    return r;
}
__device__ __forceinline__ void split_pair(float x0, float x1,
                                           uint32_t& hi, uint32_t& lo) {
    hi = pack_bf16x2(x0, x1);
    float h0 = __uint_as_float(hi << 16);
    float h1 = __uint_as_float(hi & 0xffff0000u);
    lo = pack_bf16x2(x0 - h0, x1 - h1);
}
__device__ __forceinline__ void mmabf(float c[4], const uint32_t a[4],
                                      const uint32_t b[2]) {
    asm volatile(
        "mma.sync.aligned.m16n8k16.row.col.f32.bf16.bf16.f32 "
        "{%0,%1,%2,%3},{%4,%5,%6,%7},{%8,%9},{%0,%1,%2,%3};"
        : "+f"(c[0]), "+f"(c[1]), "+f"(c[2]), "+f"(c[3])
        : "r"(a[0]), "r"(a[1]), "r"(a[2]), "r"(a[3]), "r"(b[0]), "r"(b[1]));
}
__device__ __forceinline__ void mmabf_x3(float c[4],
                                         const uint32_t aH[4], const uint32_t aL[4],
                                         const uint32_t bH[2], const uint32_t bL[2]) {
    mmabf(c, aH, bH);
    mmabf(c, aH, bL);
    mmabf(c, aL, bH);
}

// ----------------------------------------------------------------------------
// GEMM: C[M,N] = A[M,K] @ W[K,N] (+bias), bf16 x3.
// BM=128, BN=64, BK=32; 256 thr = 8 warps (4m x 2n), warp tile 32x32.
// Smem: packed bf16x2 pair arrays. A [m][kpair] stride 20 (conflict-free:
// (20g+t)%32 all-distinct). B transposed [n][kpair] stride 20.
// ----------------------------------------------------------------------------
#define GSTR 20

__global__ __launch_bounds__(256, 2)
void gemm_tc(const float* __restrict__ A, const float* __restrict__ W,
             float* __restrict__ C, const float* __restrict__ bias,
             int M, int N, int K)
{
    __shared__ uint32_t AhS[128 * GSTR], AlS[128 * GSTR];
    __shared__ uint32_t BhS[64 * GSTR],  BlS[64 * GSTR];

    const int tid = threadIdx.x;
    const int lane = tid & 31, warp = tid >> 5;
    const int wm = warp & 3, wn = warp >> 2;
    const int g = lane >> 2, t = lane & 3;
    const int m0 = blockIdx.y * 128, n0 = blockIdx.x * 64;

    // A staging: thread -> row lm, k half lk (16 k)
    const int lm = tid >> 1, lk = (tid & 1) * 16;
    // B staging: thread -> 2k x 4n block
    const int kb = tid >> 4;          // 0..15 -> k rows 2kb,2kb+1
    const int nb = (tid & 15) * 4;    // n cols

    float acc[2][4][4];
    #pragma unroll
    for (int mt = 0; mt < 2; mt++)
        #pragma unroll
        for (int nt = 0; nt < 4; nt++)
            #pragma unroll
            for (int i = 0; i < 4; i++) acc[mt][nt][i] = 0.f;

    for (int k0 = 0; k0 < K; k0 += 32) {
        // stage + split A
        const float* ap = A + (size_t)(m0 + lm) * K + k0 + lk;
        #pragma unroll
        for (int j = 0; j < 4; j++) {
            float4 a = *(const float4*)(ap + j * 4);
            uint32_t h0, l0, h1, l1;
            split_pair(a.x, a.y, h0, l0);
            split_pair(a.z, a.w, h1, l1);
            const int pi = lm * GSTR + lk / 2 + 2 * j;
            AhS[pi] = h0; AhS[pi + 1] = h1;
            AlS[pi] = l0; AlS[pi + 1] = l1;
        }
        // stage + split + transpose B: word = (k even, k odd) at [n][kpair]
        {
            const float* bp0 = W + (size_t)(k0 + 2 * kb) * N + n0 + nb;
            const float* bp1 = bp0 + N;
            float4 w0 = *(const float4*)bp0;
            float4 w1 = *(const float4*)bp1;
            float a0[4] = {w0.x, w0.y, w0.z, w0.w};
            float a1[4] = {w1.x, w1.y, w1.z, w1.w};
            #pragma unroll
            for (int e = 0; e < 4; e++) {
                uint32_t h, l;
                split_pair(a0[e], a1[e], h, l);
                BhS[(nb + e) * GSTR + kb] = h;
                BlS[(nb + e) * GSTR + kb] = l;
            }
        }
        __syncthreads();

        #pragma unroll
        for (int s = 0; s < 2; s++) {       // two k16 steps
            uint32_t aH[2][4], aL[2][4];
            #pragma unroll
            for (int mt = 0; mt < 2; mt++) {
                const int r0 = (wm * 32 + mt * 16 + g) * GSTR;
                const int r1 = r0 + 8 * GSTR;
                aH[mt][0] = AhS[r0 + s * 8 + t];
                aH[mt][1] = AhS[r1 + s * 8 + t];
                aH[mt][2] = AhS[r0 + s * 8 + t + 4];
                aH[mt][3] = AhS[r1 + s * 8 + t + 4];
                aL[mt][0] = AlS[r0 + s * 8 + t];
                aL[mt][1] = AlS[r1 + s * 8 + t];
                aL[mt][2] = AlS[r0 + s * 8 + t + 4];
                aL[mt][3] = AlS[r1 + s * 8 + t + 4];
            }
            #pragma unroll
            for (int nt = 0; nt < 4; nt++) {
                const int nc = (wn * 32 + nt * 8 + g) * GSTR;
                uint32_t bH[2], bL[2];
                bH[0] = BhS[nc + s * 8 + t];
                bH[1] = BhS[nc + s * 8 + t + 4];
                bL[0] = BlS[nc + s * 8 + t];
                bL[1] = BlS[nc + s * 8 + t + 4];
                mmabf_x3(acc[0][nt], aH[0], aL[0], bH, bL);
                mmabf_x3(acc[1][nt], aH[1], aL[1], bH, bL);
            }
        }
        __syncthreads();
    }

    #pragma unroll
    for (int mt = 0; mt < 2; mt++) {
        const int r0 = m0 + wm * 32 + mt * 16 + g;
        #pragma unroll
        for (int nt = 0; nt < 4; nt++) {
            const int c0 = n0 + wn * 32 + nt * 8 + t * 2;
            float2 v0 = make_float2(acc[mt][nt][0], acc[mt][nt][1]);
            float2 v1 = make_float2(acc[mt][nt][2], acc[mt][nt][3]);
            if (bias) {
                float b0v = bias[c0], b1v = bias[c0 + 1];
                v0.x += b0v; v0.y += b1v;
                v1.x += b0v; v1.y += b1v;
            }
            *(float2*)(C + (size_t)r0 * N + c0) = v0;
            *(float2*)(C + (size_t)(r0 + 8) * N + c0) = v1;
        }
    }
}

// ----------------------------------------------------------------------------
// Flash attention, bf16 x3, P kept in registers (QK C-frag == PV A-frag for
// k16). Per CTA: 128 queries, one (b,h). 256 thr = 8 warps, warp owns 16 q.
// Smem (dynamic, packed bf16x2 words, stride 36 conflict-free):
//   Qh/Ql [128][36], Kh/Kl [64][36] ([key][dpair]),
//   Vh/Vl [64][36] transposed ([d][keypair]), msk[64].
// 2 __syncthreads per k-tile.
// ----------------------------------------------------------------------------
#define FS 36
#define FLASH_SMEM_BYTES ((2 * 128 * FS + 4 * 64 * FS) * 4 + 64 * 4)

__global__ __launch_bounds__(256, 2)
void flash_tc(const float* __restrict__ Q, const float* __restrict__ K,
              const float* __restrict__ V, const int* __restrict__ mask,
              float* __restrict__ O)
{
    extern __shared__ uint32_t fsm[];
    uint32_t* QhS = fsm;
    uint32_t* QlS = QhS + 128 * FS;
    uint32_t* KhS = QlS + 128 * FS;
    uint32_t* KlS = KhS + 64 * FS;
    uint32_t* VhS = KlS + 64 * FS;
    uint32_t* VlS = VhS + 64 * FS;
    float* msk = (float*)(VlS + 64 * FS);

    const int bh = blockIdx.y;
    const int b = bh >> 3, h = bh & 7;
    const int q0 = blockIdx.x * 128;

    const int tid = threadIdx.x;
    const int lane = tid & 31, warp = tid >> 5;
    const int g = lane >> 2, t = lane & 3;
    const int pr = warp * 16;   // warp's local q-row base (0..112)

    const float* Qb = Q + (size_t)b * NQ * INNER + (size_t)h * DHEAD;
    const float* Kb = K + (size_t)b * MK * INNER + (size_t)h * DHEAD;
    const float* Vb = V + (size_t)b * MK * INNER + (size_t)h * DHEAD;
    const int* mb = mask + (size_t)b * MK;

    // stage + split Q tile [128 q][64 d] -> packed pairs
    for (int i = tid; i < 128 * 16; i += 256) {
        const int r = i >> 4, c = (i & 15) * 4;
        float4 v = *(const float4*)(Qb + (size_t)(q0 + r) * INNER + c);
        uint32_t h0, l0, h1, l1;
        split_pair(v.x, v.y, h0, l0);
        split_pair(v.z, v.w, h1, l1);
        const int pi = r * FS + c / 2;
        QhS[pi] = h0; QhS[pi + 1] = h1;
        QlS[pi] = l0; QlS[pi + 1] = l1;
    }

    float of[8][4];
    #pragma unroll
    for (int nt = 0; nt < 8; nt++)
        #pragma unroll
        for (int i = 0; i < 4; i++) of[nt][i] = 0.f;
    float mrow0 = -3.0e38f, mrow1 = -3.0e38f, lrow0 = 0.f, lrow1 = 0.f;
    const float scale = 0.125f;

    for (int kt = 0; kt < MK; kt += 64) {
        __syncthreads();   // prev-iter K/V reads done; Q staged (iter 0)

        // stage + split K tile [64 key][64 d]
        for (int i = tid; i < 64 * 16; i += 256) {
            const int r = i >> 4, c = (i & 15) * 4;
            float4 v = *(const float4*)(Kb + (size_t)(kt + r) * INNER + c);
            uint32_t h0, l0, h1, l1;
            split_pair(v.x, v.y, h0, l0);
            split_pair(v.z, v.w, h1, l1);
            const int pi = r * FS + c / 2;
            KhS[pi] = h0; KhS[pi + 1] = h1;
            KlS[pi] = l0; KlS[pi + 1] = l1;
        }
        // stage + split + transpose V tile -> [d][keypair]
        #pragma unroll
        for (int j = 0; j < 2; j++) {
            const int blk = tid + j * 256;         // 512 blocks of 2k x 4d
            const int kb2 = blk >> 4;              // 0..31 -> keys 2kb2,2kb2+1
            const int db = (blk & 15) * 4;
            const float* vp0 = Vb + (size_t)(kt + 2 * kb2) * INNER + db;
            const float* vp1 = vp0 + INNER;
            float4 v0 = *(const float4*)vp0;
            float4 v1 = *(const float4*)vp1;
            float a0[4] = {v0.x, v0.y, v0.z, v0.w};
            float a1[4] = {v1.x, v1.y, v1.z, v1.w};
            #pragma unroll
            for (int e = 0; e < 4; e++) {
                uint32_t hh, ll;
                split_pair(a0[e], a1[e], hh, ll);
                VhS[(db + e) * FS + kb2] = hh;
                VlS[(db + e) * FS + kb2] = ll;
            }
        }
        if (tid < 64) msk[tid] = (mb[kt + tid] != 0) ? 0.f : -1.0e30f;
        __syncthreads();

        // ---- S = Q K^T (bf16 x3) ----
        float sf[8][4];
        #pragma unroll
        for (int nt = 0; nt < 8; nt++)
            #pragma unroll
            for (int i = 0; i < 4; i++) sf[nt][i] = 0.f;

        #pragma unroll
        for (int s = 0; s < 4; s++) {           // d16 steps
            uint32_t aH[4], aL[4];
            const int r0 = (pr + g) * FS, r1 = (pr + g + 8) * FS;
            aH[0] = QhS[r0 + s * 8 + t];
            aH[1] = QhS[r1 + s * 8 + t];
            aH[2] = QhS[r0 + s * 8 + t + 4];
            aH[3] = QhS[r1 + s * 8 + t + 4];
            aL[0] = QlS[r0 + s * 8 + t];
            aL[1] = QlS[r1 + s * 8 + t];
            aL[2] = QlS[r0 + s * 8 + t + 4];
            aL[3] = QlS[r1 + s * 8 + t + 4];
            #pragma unroll
            for (int nt = 0; nt < 8; nt++) {
                const int kr = (nt * 8 + g) * FS;
                uint32_t bH[2], bL[2];
                bH[0] = KhS[kr + s * 8 + t];
                bH[1] = KhS[kr + s * 8 + t + 4];
                bL[0] = KlS[kr + s * 8 + t];
                bL[1] = KlS[kr + s * 8 + t + 4];
                mmabf_x3(sf[nt], aH, aL, bH, bL);
            }
        }

        // ---- scale + mask + online softmax ----
        float mx0 = -3.0e38f, mx1 = -3.0e38f;
        #pragma unroll
        for (int nt = 0; nt < 8; nt++) {
            float mk0 = msk[nt * 8 + 2 * t], mk1 = msk[nt * 8 + 2 * t + 1];
            sf[nt][0] = sf[nt][0] * scale + mk0;
            sf[nt][1] = sf[nt][1] * scale + mk1;
            sf[nt][2] = sf[nt][2] * scale + mk0;
            sf[nt][3] = sf[nt][3] * scale + mk1;
            mx0 = fmaxf(mx0, fmaxf(sf[nt][0], sf[nt][1]));
            mx1 = fmaxf(mx1, fmaxf(sf[nt][2], sf[nt][3]));
        }
        mx0 = fmaxf(mx0, __shfl_xor_sync(0xffffffffu, mx0, 1));
        mx0 = fmaxf(mx0, __shfl_xor_sync(0xffffffffu, mx0, 2));
        mx1 = fmaxf(mx1, __shfl_xor_sync(0xffffffffu, mx1, 1));
        mx1 = fmaxf(mx1, __shfl_xor_sync(0xffffffffu, mx1, 2));

        const float mn0 = fmaxf(mrow0, mx0), mn1 = fmaxf(mrow1, mx1);
        const float corr0 = __expf(mrow0 - mn0), corr1 = __expf(mrow1 - mn1);
        float ls0 = 0.f, ls1 = 0.f;
        #pragma unroll
        for (int nt = 0; nt < 8; nt++) {
            sf[nt][0] = __expf(sf[nt][0] - mn0);
            sf[nt][1] = __expf(sf[nt][1] - mn0);
            sf[nt][2] = __expf(sf[nt][2] - mn1);
            sf[nt][3] = __expf(sf[nt][3] - mn1);
            ls0 += sf[nt][0] + sf[nt][1];
            ls1 += sf[nt][2] + sf[nt][3];
        }
        ls0 += __shfl_xor_sync(0xffffffffu, ls0, 1);
        ls0 += __shfl_xor_sync(0xffffffffu, ls0, 2);
        ls1 += __shfl_xor_sync(0xffffffffu, ls1, 1);
        ls1 += __shfl_xor_sync(0xffffffffu, ls1, 2);

        lrow0 = lrow0 * corr0 + ls0; mrow0 = mn0;
        lrow1 = lrow1 * corr1 + ls1; mrow1 = mn1;

        #pragma unroll
        for (int nt = 0; nt < 8; nt++) {
            of[nt][0] *= corr0; of[nt][1] *= corr0;
            of[nt][2] *= corr1; of[nt][3] *= corr1;
        }

        // ---- O += P @ V, P built in registers from sf (C-frag == A-frag) ----
        #pragma unroll
        for (int u = 0; u < 4; u++) {           // key16 steps
            uint32_t pH[4], pL[4];
            split_pair(sf[2 * u][0],     sf[2 * u][1],     pH[0], pL[0]);
            split_pair(sf[2 * u][2],     sf[2 * u][3],     pH[1], pL[1]);
            split_pair(sf[2 * u + 1][0], sf[2 * u + 1][1], pH[2], pL[2]);
            split_pair(sf[2 * u + 1][2], sf[2 * u + 1][3], pH[3], pL[3]);
            #pragma unroll
            for (int nt = 0; nt < 8; nt++) {    // d columns
                const int vr = (nt * 8 + g) * FS;
                uint32_t bH[2], bL[2];
                bH[0] = VhS[vr + u * 8 + t];
                bH[1] = VhS[vr + u * 8 + t + 4];
                bL[0] = VlS[vr + u * 8 + t];
                bL[1] = VlS[vr + u * 8 + t + 4];
                mmabf_x3(of[nt], pH, pL, bH, bL);
            }
        }
    }

    // epilogue
    const float inv0 = 1.f / lrow0, inv1 = 1.f / lrow1;
    const int qa = q0 + pr + g;
    #pragma unroll
    for (int nt = 0; nt < 8; nt++) {
        const int col = h * DHEAD + nt * 8 + 2 * t;
        float2 v0 = make_float2(of[nt][0] * inv0, of[nt][1] * inv0);
        float2 v1 = make_float2(of[nt][2] * inv1, of[nt][3] * inv1);
        *(float2*)(O + (size_t)(b * NQ + qa) * INNER + col) = v0;
        *(float2*)(O + (size_t)(b * NQ + qa + 8) * INNER + col) = v1;
    }
}

// ----------------------------------------------------------------------------
// kernel_launch
// Inputs: 0=x, 1=context, 2=mask (int32), 3=Wq, 4=Wk, 5=Wv, 6=Wo, 7=bo
// ----------------------------------------------------------------------------
extern "C" void kernel_launch(void* const* d_in, const int* in_sizes, int n_in,
                              void* d_out, int out_size)
{
    const float* x    = (const float*)d_in[0];
    const float* ctx  = (const float*)d_in[1];
    const int*   mask = (const int*)d_in[2];
    const float* Wq   = (const float*)d_in[3];
    const float* Wk   = (const float*)d_in[4];
    const float* Wv   = (const float*)d_in[5];
    const float* Wo   = (const float*)d_in[6];
    const float* bo   = (const float*)d_in[7];
    float* out = (float*)d_out;

    float *pQ, *pK, *pV, *pO;
    cudaGetSymbolAddress((void**)&pQ, g_Q);
    cudaGetSymbolAddress((void**)&pK, g_K);
    cudaGetSymbolAddress((void**)&pV, g_V);
    cudaGetSymbolAddress((void**)&pO, g_O);

    const int rowsX = BSZ * NQ;   // 8192
    const int rowsC = BSZ * MK;   // 8192

    cudaFuncSetAttribute(flash_tc, cudaFuncAttributeMaxDynamicSharedMemorySize,
                         FLASH_SMEM_BYTES);

    {   // projections
        dim3 gq(INNER / 64, rowsX / 128);
        gemm_tc<<<gq, 256>>>(x, Wq, pQ, nullptr, rowsX, INNER, DIMX);
        dim3 gk(INNER / 64, rowsC / 128);
        gemm_tc<<<gk, 256>>>(ctx, Wk, pK, nullptr, rowsC, INNER, CTXD);
        gemm_tc<<<gk, 256>>>(ctx, Wv, pV, nullptr, rowsC, INNER, CTXD);
    }
    {   // flash attention
        dim3 grid(NQ / 128, BSZ * HEADS);
        flash_tc<<<grid, 256, FLASH_SMEM_BYTES>>>(pQ, pK, pV, mask, pO);
    }
    {   // out = O @ Wo + bo
        dim3 go(DIMX / 64, rowsX / 128);
        gemm_tc<<<go, 256>>>(pO, Wo, out, bo, rowsX, DIMX, INNER);
    }
}

// round 8
// speedup vs baseline: 1.9379x; 1.1380x over previous
#include <cuda_runtime.h>
#include <math.h>
#include <stdint.h>

// Problem constants
#define BSZ   4
#define NQ    2048
#define MK    2048
#define DIMX  1024
#define CTXD  1024
#define HEADS 8
#define DHEAD 64
#define INNER 512   // HEADS * DHEAD

// Scratch (allocation-free rule: __device__ globals)
__device__ float g_Q[(size_t)BSZ * NQ * INNER];
__device__ float g_K[(size_t)BSZ * MK * INNER];
__device__ float g_V[(size_t)BSZ * MK * INNER];
__device__ float g_O[(size_t)BSZ * NQ * INNER];

// ============================================================================
// bf16 x3 helpers + ldmatrix
// ============================================================================
__device__ __forceinline__ uint32_t pack_bf16x2(float e0, float e1) {
    uint32_t r;
    asm("cvt.rn.bf16x2.f32 %0, %1, %2;" : "=r"(r) : "f"(e1), "f"(e0));
    return r;
}
__device__ __forceinline__ void split_pair(float x0, float x1,
                                           uint32_t& hi, uint32_t& lo) {
    hi = pack_bf16x2(x0, x1);
    float h0 = __uint_as_float(hi << 16);
    float h1 = __uint_as_float(hi & 0xffff0000u);
    lo = pack_bf16x2(x0 - h0, x1 - h1);
}
__device__ __forceinline__ void mmabf(float c[4], const uint32_t a[4],
                                      const uint32_t b[2]) {
    asm volatile(
        "mma.sync.aligned.m16n8k16.row.col.f32.bf16.bf16.f32 "
        "{%0,%1,%2,%3},{%4,%5,%6,%7},{%8,%9},{%0,%1,%2,%3};"
        : "+f"(c[0]), "+f"(c[1]), "+f"(c[2]), "+f"(c[3])
        : "r"(a[0]), "r"(a[1]), "r"(a[2]), "r"(a[3]), "r"(b[0]), "r"(b[1]));
}
__device__ __forceinline__ void mmabf_x3(float c[4],
                                         const uint32_t aH[4], const uint32_t aL[4],
                                         const uint32_t bH[2], const uint32_t bL[2]) {
    mmabf(c, aH, bH);
    mmabf(c, aH, bL);
    mmabf(c, aL, bH);
}
__device__ __forceinline__ void ldsm_x4(uint32_t* r, uint32_t a) {
    asm volatile("ldmatrix.sync.aligned.m8n8.x4.shared.b16 {%0,%1,%2,%3}, [%4];"
                 : "=r"(r[0]), "=r"(r[1]), "=r"(r[2]), "=r"(r[3]) : "r"(a));
}
__device__ __forceinline__ void ldsm_x2(uint32_t* r, uint32_t a) {
    asm volatile("ldmatrix.sync.aligned.m8n8.x2.shared.b16 {%0,%1}, [%2];"
                 : "=r"(r[0]), "=r"(r[1]) : "r"(a));
}
__device__ __forceinline__ uint32_t smem_u32(const void* p) {
    uint32_t a;
    asm("{ .reg .u64 t; cvta.to.shared.u64 t, %1; cvt.u32.u64 %0, t; }"
        : "=r"(a) : "l"(p));
    return a;
}

// ============================================================================
// GEMM: C[M,N] = A[M,K] @ W[K,N] (+bias), bf16 x3, ldmatrix fragment loads.
// BM=128, BN=128, BK=32; 256 thr = 8 warps (4m x 2n), warp tile 32x64.
// Smem (static, packed bf16x2 words): A [m][kpair] stride 20,
// B transposed [n][kpair] stride 20. Both 16B-aligned rows, conflict-free.
// ============================================================================
#define GSTR 20

__global__ __launch_bounds__(256, 2)
void gemm_tc(const float* __restrict__ A, const float* __restrict__ W,
             float* __restrict__ C, const float* __restrict__ bias,
             int M, int N, int K)
{
    __shared__ uint32_t AhS[128 * GSTR], AlS[128 * GSTR];
    __shared__ uint32_t BhS[128 * GSTR], BlS[128 * GSTR];

    const int tid = threadIdx.x;
    const int lane = tid & 31, warp = tid >> 5;
    const int wm = warp & 3, wn = warp >> 2;
    const int g = lane >> 2, t = lane & 3;
    const int m0 = blockIdx.y * 128, n0 = blockIdx.x * 128;

    // ldmatrix lane-derived selectors
    const int arow_sel = (lane & 7) + (lane & 8);     // A x4: row within 16
    const int acol_sel = (lane & 16) ? 4 : 0;         // A x4: k-half word off
    const int brow_sel = lane & 7;                    // B x2: row within 8
    const int bcol_sel = (lane & 8) ? 4 : 0;          // B x2: k-half word off

    const uint32_t ah_b = smem_u32(AhS), al_b = smem_u32(AlS);
    const uint32_t bh_b = smem_u32(BhS), bl_b = smem_u32(BlS);

    // staging maps
    const int lm = tid >> 1, lk = (tid & 1) * 16;     // A: row, k-half
    const int kb = tid >> 4;                          // B: k rows 2kb,2kb+1
    const int nb = (tid & 15) * 4;                    // B: n cols (+0/+64)

    float acc[2][8][4];
    #pragma unroll
    for (int mt = 0; mt < 2; mt++)
        #pragma unroll
        for (int nt = 0; nt < 8; nt++)
            #pragma unroll
            for (int i = 0; i < 4; i++) acc[mt][nt][i] = 0.f;

    for (int k0 = 0; k0 < K; k0 += 32) {
        // stage + split A [128 m][32 k]
        const float* ap = A + (size_t)(m0 + lm) * K + k0 + lk;
        #pragma unroll
        for (int j = 0; j < 4; j++) {
            float4 a = *(const float4*)(ap + j * 4);
            uint32_t h0, l0, h1, l1;
            split_pair(a.x, a.y, h0, l0);
            split_pair(a.z, a.w, h1, l1);
            const int pi = lm * GSTR + lk / 2 + 2 * j;
            AhS[pi] = h0; AhS[pi + 1] = h1;
            AlS[pi] = l0; AlS[pi + 1] = l1;
        }
        // stage + split + transpose B: W[k][n] -> Bs[n][kpair], 128 n cols
        #pragma unroll
        for (int j = 0; j < 2; j++) {
            const int nb2 = nb + j * 64;
            const float* bp0 = W + (size_t)(k0 + 2 * kb) * N + n0 + nb2;
            const float* bp1 = bp0 + N;
            float4 w0 = *(const float4*)bp0;
            float4 w1 = *(const float4*)bp1;
            float a0[4] = {w0.x, w0.y, w0.z, w0.w};
            float a1[4] = {w1.x, w1.y, w1.z, w1.w};
            #pragma unroll
            for (int e = 0; e < 4; e++) {
                uint32_t h, l;
                split_pair(a0[e], a1[e], h, l);
                BhS[(nb2 + e) * GSTR + kb] = h;
                BlS[(nb2 + e) * GSTR + kb] = l;
            }
        }
        __syncthreads();

        #pragma unroll
        for (int s = 0; s < 2; s++) {       // two k16 steps
            uint32_t aH[2][4], aL[2][4];
            #pragma unroll
            for (int mt = 0; mt < 2; mt++) {
                const uint32_t aoff =
                    (uint32_t)(((wm * 32 + mt * 16 + arow_sel) * GSTR +
                                s * 8 + acol_sel) * 4);
                ldsm_x4(aH[mt], ah_b + aoff);
                ldsm_x4(aL[mt], al_b + aoff);
            }
            #pragma unroll
            for (int nt = 0; nt < 8; nt++) {
                const uint32_t boff =
                    (uint32_t)(((wn * 64 + nt * 8 + brow_sel) * GSTR +
                                s * 8 + bcol_sel) * 4);
                uint32_t bH[2], bL[2];
                ldsm_x2(bH, bh_b + boff);
                ldsm_x2(bL, bl_b + boff);
                mmabf_x3(acc[0][nt], aH[0], aL[0], bH, bL);
                mmabf_x3(acc[1][nt], aH[1], aL[1], bH, bL);
            }
        }
        __syncthreads();
    }

    #pragma unroll
    for (int mt = 0; mt < 2; mt++) {
        const int r0 = m0 + wm * 32 + mt * 16 + g;
        #pragma unroll
        for (int nt = 0; nt < 8; nt++) {
            const int c0 = n0 + wn * 64 + nt * 8 + t * 2;
            float2 v0 = make_float2(acc[mt][nt][0], acc[mt][nt][1]);
            float2 v1 = make_float2(acc[mt][nt][2], acc[mt][nt][3]);
            if (bias) {
                float b0v = bias[c0], b1v = bias[c0 + 1];
                v0.x += b0v; v0.y += b1v;
                v1.x += b0v; v1.y += b1v;
            }
            *(float2*)(C + (size_t)r0 * N + c0) = v0;
            *(float2*)(C + (size_t)(r0 + 8) * N + c0) = v1;
        }
    }
}

// ============================================================================
// Flash attention, bf16 x3, P in registers, ldmatrix fragment loads.
// Per CTA: 128 queries, one (b,h). 256 thr = 8 warps, warp owns 16 q.
// Smem (dynamic, packed bf16x2 words, stride 36):
//   Qh/Ql [128][36], Kh/Kl [64][36] ([key][dpair]),
//   Vh/Vl [64][36] transposed ([d][keypair]), msk[64].
// ============================================================================
#define FS 36
#define FL_QH 0
#define FL_QL (128 * FS * 4)
#define FL_KH (2 * 128 * FS * 4)
#define FL_KL (FL_KH + 64 * FS * 4)
#define FL_VH (FL_KL + 64 * FS * 4)
#define FL_VL (FL_VH + 64 * FS * 4)
#define FLASH_SMEM_BYTES (FL_VL + 64 * FS * 4 + 64 * 4)

__global__ __launch_bounds__(256, 2)
void flash_tc(const float* __restrict__ Q, const float* __restrict__ K,
              const float* __restrict__ V, const int* __restrict__ mask,
              float* __restrict__ O)
{
    extern __shared__ uint32_t fsm[];
    uint32_t* QhS = fsm;
    uint32_t* QlS = QhS + 128 * FS;
    uint32_t* KhS = QlS + 128 * FS;
    uint32_t* KlS = KhS + 64 * FS;
    uint32_t* VhS = KlS + 64 * FS;
    uint32_t* VlS = VhS + 64 * FS;
    float* msk = (float*)(VlS + 64 * FS);
    const uint32_t smb = smem_u32(fsm);

    const int bh = blockIdx.y;
    const int b = bh >> 3, h = bh & 7;
    const int q0 = blockIdx.x * 128;

    const int tid = threadIdx.x;
    const int lane = tid & 31, warp = tid >> 5;
    const int g = lane >> 2, t = lane & 3;
    const int pr = warp * 16;

    // ldmatrix lane-derived selectors
    const int arow_sel = (lane & 7) + (lane & 8);
    const int acol_sel = (lane & 16) ? 4 : 0;
    const int brow_sel = lane & 7;
    const int bcol_sel = (lane & 8) ? 4 : 0;

    const float* Qb = Q + (size_t)b * NQ * INNER + (size_t)h * DHEAD;
    const float* Kb = K + (size_t)b * MK * INNER + (size_t)h * DHEAD;
    const float* Vb = V + (size_t)b * MK * INNER + (size_t)h * DHEAD;
    const int* mb = mask + (size_t)b * MK;

    // stage + split Q tile [128 q][64 d]
    for (int i = tid; i < 128 * 16; i += 256) {
        const int r = i >> 4, c = (i & 15) * 4;
        float4 v = *(const float4*)(Qb + (size_t)(q0 + r) * INNER + c);
        uint32_t h0, l0, h1, l1;
        split_pair(v.x, v.y, h0, l0);
        split_pair(v.z, v.w, h1, l1);
        const int pi = r * FS + c / 2;
        QhS[pi] = h0; QhS[pi + 1] = h1;
        QlS[pi] = l0; QlS[pi + 1] = l1;
    }

    float of[8][4];
    #pragma unroll
    for (int nt = 0; nt < 8; nt++)
        #pragma unroll
        for (int i = 0; i < 4; i++) of[nt][i] = 0.f;
    float mrow0 = -3.0e38f, mrow1 = -3.0e38f, lrow0 = 0.f, lrow1 = 0.f;
    const float scale = 0.125f;

    for (int kt = 0; kt < MK; kt += 64) {
        __syncthreads();   // prev-iter K/V reads done; Q staged (iter 0)

        // stage + split K tile [64 key][64 d]
        for (int i = tid; i < 64 * 16; i += 256) {
            const int r = i >> 4, c = (i & 15) * 4;
            float4 v = *(const float4*)(Kb + (size_t)(kt + r) * INNER + c);
            uint32_t h0, l0, h1, l1;
            split_pair(v.x, v.y, h0, l0);
            split_pair(v.z, v.w, h1, l1);
            const int pi = r * FS + c / 2;
            KhS[pi] = h0; KhS[pi + 1] = h1;
            KlS[pi] = l0; KlS[pi + 1] = l1;
        }
        // stage + split + transpose V tile -> [d][keypair]
        #pragma unroll
        for (int j = 0; j < 2; j++) {
            const int blk = tid + j * 256;
            const int kb2 = blk >> 4;
            const int db = (blk & 15) * 4;
            const float* vp0 = Vb + (size_t)(kt + 2 * kb2) * INNER + db;
            const float* vp1 = vp0 + INNER;
            float4 v0 = *(const float4*)vp0;
            float4 v1 = *(const float4*)vp1;
            float a0[4] = {v0.x, v0.y, v0.z, v0.w};
            float a1[4] = {v1.x, v1.y, v1.z, v1.w};
            #pragma unroll
            for (int e = 0; e < 4; e++) {
                uint32_t hh, ll;
                split_pair(a0[e], a1[e], hh, ll);
                VhS[(db + e) * FS + kb2] = hh;
                VlS[(db + e) * FS + kb2] = ll;
            }
        }
        if (tid < 64) msk[tid] = (mb[kt + tid] != 0) ? 0.f : -1.0e30f;
        __syncthreads();

        // ---- S = Q K^T (bf16 x3, ldmatrix) ----
        float sf[8][4];
        #pragma unroll
        for (int nt = 0; nt < 8; nt++)
            #pragma unroll
            for (int i = 0; i < 4; i++) sf[nt][i] = 0.f;

        #pragma unroll
        for (int s = 0; s < 4; s++) {           // d16 steps
            uint32_t aH[4], aL[4];
            const uint32_t qoff =
                (uint32_t)(((pr + arow_sel) * FS + s * 8 + acol_sel) * 4);
            ldsm_x4(aH, smb + FL_QH + qoff);
            ldsm_x4(aL, smb + FL_QL + qoff);
            #pragma unroll
            for (int nt = 0; nt < 8; nt++) {
                const uint32_t koff =
                    (uint32_t)(((nt * 8 + brow_sel) * FS + s * 8 + bcol_sel) * 4);
                uint32_t bH[2], bL[2];
                ldsm_x2(bH, smb + FL_KH + koff);
                ldsm_x2(bL, smb + FL_KL + koff);
                mmabf_x3(sf[nt], aH, aL, bH, bL);
            }
        }

        // ---- scale + mask + online softmax ----
        float mx0 = -3.0e38f, mx1 = -3.0e38f;
        #pragma unroll
        for (int nt = 0; nt < 8; nt++) {
            float mk0 = msk[nt * 8 + 2 * t], mk1 = msk[nt * 8 + 2 * t + 1];
            sf[nt][0] = sf[nt][0] * scale + mk0;
            sf[nt][1] = sf[nt][1] * scale + mk1;
            sf[nt][2] = sf[nt][2] * scale + mk0;
            sf[nt][3] = sf[nt][3] * scale + mk1;
            mx0 = fmaxf(mx0, fmaxf(sf[nt][0], sf[nt][1]));
            mx1 = fmaxf(mx1, fmaxf(sf[nt][2], sf[nt][3]));
        }
        mx0 = fmaxf(mx0, __shfl_xor_sync(0xffffffffu, mx0, 1));
        mx0 = fmaxf(mx0, __shfl_xor_sync(0xffffffffu, mx0, 2));
        mx1 = fmaxf(mx1, __shfl_xor_sync(0xffffffffu, mx1, 1));
        mx1 = fmaxf(mx1, __shfl_xor_sync(0xffffffffu, mx1, 2));

        const float mn0 = fmaxf(mrow0, mx0), mn1 = fmaxf(mrow1, mx1);
        const float corr0 = __expf(mrow0 - mn0), corr1 = __expf(mrow1 - mn1);
        float ls0 = 0.f, ls1 = 0.f;
        #pragma unroll
        for (int nt = 0; nt < 8; nt++) {
            sf[nt][0] = __expf(sf[nt][0] - mn0);
            sf[nt][1] = __expf(sf[nt][1] - mn0);
            sf[nt][2] = __expf(sf[nt][2] - mn1);
            sf[nt][3] = __expf(sf[nt][3] - mn1);
            ls0 += sf[nt][0] + sf[nt][1];
            ls1 += sf[nt][2] + sf[nt][3];
        }
        ls0 += __shfl_xor_sync(0xffffffffu, ls0, 1);
        ls0 += __shfl_xor_sync(0xffffffffu, ls0, 2);
        ls1 += __shfl_xor_sync(0xffffffffu, ls1, 1);
        ls1 += __shfl_xor_sync(0xffffffffu, ls1, 2);

        lrow0 = lrow0 * corr0 + ls0; mrow0 = mn0;
        lrow1 = lrow1 * corr1 + ls1; mrow1 = mn1;

        #pragma unroll
        for (int nt = 0; nt < 8; nt++) {
            of[nt][0] *= corr0; of[nt][1] *= corr0;
            of[nt][2] *= corr1; of[nt][3] *= corr1;
        }

        // ---- O += P @ V (P split in registers; V via ldmatrix) ----
        #pragma unroll
        for (int u = 0; u < 4; u++) {           // key16 steps
            uint32_t pH[4], pL[4];
            split_pair(sf[2 * u][0],     sf[2 * u][1],     pH[0], pL[0]);
            split_pair(sf[2 * u][2],     sf[2 * u][3],     pH[1], pL[1]);
            split_pair(sf[2 * u + 1][0], sf[2 * u + 1][1], pH[2], pL[2]);
            split_pair(sf[2 * u + 1][2], sf[2 * u + 1][3], pH[3], pL[3]);
            #pragma unroll
            for (int nt = 0; nt < 8; nt++) {    // d columns
                const uint32_t voff =
                    (uint32_t)(((nt * 8 + brow_sel) * FS + u * 8 + bcol_sel) * 4);
                uint32_t bH[2], bL[2];
                ldsm_x2(bH, smb + FL_VH + voff);
                ldsm_x2(bL, smb + FL_VL + voff);
                mmabf_x3(of[nt], pH, pL, bH, bL);
            }
        }
    }

    // epilogue
    const float inv0 = 1.f / lrow0, inv1 = 1.f / lrow1;
    const int qa = q0 + pr + g;
    #pragma unroll
    for (int nt = 0; nt < 8; nt++) {
        const int col = h * DHEAD + nt * 8 + 2 * t;
        float2 v0 = make_float2(of[nt][0] * inv0, of[nt][1] * inv0);
        float2 v1 = make_float2(of[nt][2] * inv1, of[nt][3] * inv1);
        *(float2*)(O + (size_t)(b * NQ + qa) * INNER + col) = v0;
        *(float2*)(O + (size_t)(b * NQ + qa + 8) * INNER + col) = v1;
    }
}

// ----------------------------------------------------------------------------
// kernel_launch
// Inputs: 0=x, 1=context, 2=mask (int32), 3=Wq, 4=Wk, 5=Wv, 6=Wo, 7=bo
// ----------------------------------------------------------------------------
extern "C" void kernel_launch(void* const* d_in, const int* in_sizes, int n_in,
                              void* d_out, int out_size)
{
    const float* x    = (const float*)d_in[0];
    const float* ctx  = (const float*)d_in[1];
    const int*   mask = (const int*)d_in[2];
    const float* Wq   = (const float*)d_in[3];
    const float* Wk   = (const float*)d_in[4];
    const float* Wv   = (const float*)d_in[5];
    const float* Wo   = (const float*)d_in[6];
    const float* bo   = (const float*)d_in[7];
    float* out = (float*)d_out;

    float *pQ, *pK, *pV, *pO;
    cudaGetSymbolAddress((void**)&pQ, g_Q);
    cudaGetSymbolAddress((void**)&pK, g_K);
    cudaGetSymbolAddress((void**)&pV, g_V);
    cudaGetSymbolAddress((void**)&pO, g_O);

    const int rowsX = BSZ * NQ;   // 8192
    const int rowsC = BSZ * MK;   // 8192

    cudaFuncSetAttribute(flash_tc, cudaFuncAttributeMaxDynamicSharedMemorySize,
                         FLASH_SMEM_BYTES);

    {   // projections
        dim3 gq(INNER / 128, rowsX / 128);
        gemm_tc<<<gq, 256>>>(x, Wq, pQ, nullptr, rowsX, INNER, DIMX);
        dim3 gk(INNER / 128, rowsC / 128);
        gemm_tc<<<gk, 256>>>(ctx, Wk, pK, nullptr, rowsC, INNER, CTXD);
        gemm_tc<<<gk, 256>>>(ctx, Wv, pV, nullptr, rowsC, INNER, CTXD);
    }
    {   // flash attention
        dim3 grid(NQ / 128, BSZ * HEADS);
        flash_tc<<<grid, 256, FLASH_SMEM_BYTES>>>(pQ, pK, pV, mask, pO);
    }
    {   // out = O @ Wo + bo
        dim3 go(DIMX / 128, rowsX / 128);
        gemm_tc<<<go, 256>>>(pO, Wo, out, bo, rowsX, DIMX, INNER);
    }
}

// round 9
// speedup vs baseline: 2.4233x; 1.2505x over previous
#include <cuda_runtime.h>
#include <math.h>
#include <stdint.h>

// Problem constants
#define BSZ   4
#define NQ    2048
#define MK    2048
#define DIMX  1024
#define CTXD  1024
#define HEADS 8
#define DHEAD 64
#define INNER 512   // HEADS * DHEAD

// ============================================================================
// Packed bf16 hi/lo scratch in gmem (allocation-free: __device__ globals)
// ============================================================================
__device__ uint32_t g_xH[(size_t)8192 * 512], g_xL[(size_t)8192 * 512];
__device__ uint32_t g_cH[(size_t)8192 * 512], g_cL[(size_t)8192 * 512];
__device__ uint32_t g_WqH[512 * 512],  g_WqL[512 * 512];
__device__ uint32_t g_WkH[512 * 512],  g_WkL[512 * 512];
__device__ uint32_t g_WvH[512 * 512],  g_WvL[512 * 512];
__device__ uint32_t g_WoH[1024 * 256], g_WoL[1024 * 256];
__device__ uint32_t g_QH[(size_t)32 * 2048 * 32], g_QL[(size_t)32 * 2048 * 32];
__device__ uint32_t g_KH[(size_t)32 * 2048 * 32], g_KL[(size_t)32 * 2048 * 32];
__device__ uint32_t g_VtH[(size_t)32 * 64 * 1024], g_VtL[(size_t)32 * 64 * 1024];
__device__ float    g_Vf[(size_t)8192 * 512];
__device__ uint32_t g_OH2[(size_t)8192 * 256], g_OL2[(size_t)8192 * 256];

// ============================================================================
// bf16 x3 helpers, ldmatrix, cp.async
// ============================================================================
__device__ __forceinline__ uint32_t pack_bf16x2(float e0, float e1) {
    uint32_t r;
    asm("cvt.rn.bf16x2.f32 %0, %1, %2;" : "=r"(r) : "f"(e1), "f"(e0));
    return r;
}
__device__ __forceinline__ void split_pair(float x0, float x1,
                                           uint32_t& hi, uint32_t& lo) {
    hi = pack_bf16x2(x0, x1);
    float h0 = __uint_as_float(hi << 16);
    float h1 = __uint_as_float(hi & 0xffff0000u);
    lo = pack_bf16x2(x0 - h0, x1 - h1);
}
__device__ __forceinline__ void mmabf(float c[4], const uint32_t a[4],
                                      const uint32_t b[2]) {
    asm volatile(
        "mma.sync.aligned.m16n8k16.row.col.f32.bf16.bf16.f32 "
        "{%0,%1,%2,%3},{%4,%5,%6,%7},{%8,%9},{%0,%1,%2,%3};"
        : "+f"(c[0]), "+f"(c[1]), "+f"(c[2]), "+f"(c[3])
        : "r"(a[0]), "r"(a[1]), "r"(a[2]), "r"(a[3]), "r"(b[0]), "r"(b[1]));
}
__device__ __forceinline__ void mmabf_x3(float c[4],
                                         const uint32_t aH[4], const uint32_t aL[4],
                                         const uint32_t bH[2], const uint32_t bL[2]) {
    mmabf(c, aH, bH);
    mmabf(c, aH, bL);
    mmabf(c, aL, bH);
}
__device__ __forceinline__ void ldsm_x4(uint32_t* r, uint32_t a) {
    asm volatile("ldmatrix.sync.aligned.m8n8.x4.shared.b16 {%0,%1,%2,%3}, [%4];"
                 : "=r"(r[0]), "=r"(r[1]), "=r"(r[2]), "=r"(r[3]) : "r"(a));
}
__device__ __forceinline__ void ldsm_x2(uint32_t* r, uint32_t a) {
    asm volatile("ldmatrix.sync.aligned.m8n8.x2.shared.b16 {%0,%1}, [%2];"
                 : "=r"(r[0]), "=r"(r[1]) : "r"(a));
}
__device__ __forceinline__ uint32_t smem_u32(const void* p) {
    uint32_t a;
    asm("{ .reg .u64 t; cvta.to.shared.u64 t, %1; cvt.u32.u64 %0, t; }"
        : "=r"(a) : "l"(p));
    return a;
}
__device__ __forceinline__ void cpa16(uint32_t sa, const void* g) {
    asm volatile("cp.async.cg.shared.global [%0], [%1], 16;"
                 :: "r"(sa), "l"(g) : "memory");
}
#define CP_COMMIT() asm volatile("cp.async.commit_group;" ::: "memory")
#define CP_WAIT1()  asm volatile("cp.async.wait_group 1;"  ::: "memory")
#define CP_WAIT0()  asm volatile("cp.async.wait_group 0;"  ::: "memory")

// ============================================================================
// repack_a: fp32 [R][K] -> packed hi/lo words [R][K/2] (flat)
// ============================================================================
__global__ __launch_bounds__(256)
void repack_a(const float* __restrict__ A, uint32_t* __restrict__ H,
              uint32_t* __restrict__ L, int n4)
{
    int i = blockIdx.x * 256 + threadIdx.x;
    if (i >= n4) return;
    float4 a = ((const float4*)A)[i];
    uint32_t h0, l0, h1, l1;
    split_pair(a.x, a.y, h0, l0);
    split_pair(a.z, a.w, h1, l1);
    H[2 * i] = h0; H[2 * i + 1] = h1;
    L[2 * i] = l0; L[2 * i + 1] = l1;
}

// ============================================================================
// repack_w: fp32 W[K][N] -> transposed packed [N][K/2]. grid (K/128, N/64).
// ============================================================================
__global__ __launch_bounds__(256)
void repack_w(const float* __restrict__ W, uint32_t* __restrict__ H,
              uint32_t* __restrict__ L, int K, int N)
{
    __shared__ float SM[128][68];
    const int tid = threadIdx.x;
    const int k0 = blockIdx.x * 128, n0 = blockIdx.y * 64;
    #pragma unroll
    for (int j = 0; j < 8; j++) {
        int idx = tid + j * 256;
        int r = idx >> 4, c4 = (idx & 15) * 4;
        *(float4*)&SM[r][c4] = *(const float4*)(W + (size_t)(k0 + r) * N + n0 + c4);
    }
    __syncthreads();
    #pragma unroll
    for (int j = 0; j < 16; j++) {
        int idx = tid + j * 256;
        int n = idx >> 6, kp = idx & 63;
        uint32_t h, l;
        split_pair(SM[2 * kp][n], SM[2 * kp + 1][n], h, l);
        size_t d = (size_t)(n0 + n) * (K / 2) + k0 / 2 + kp;
        H[d] = h; L[d] = l;
    }
}

// ============================================================================
// repack_v: fp32 V [B*2048][512] -> per-(b,h) transposed packed [64 d][1024 kp]
// grid (2048/128, 32)
// ============================================================================
__global__ __launch_bounds__(256)
void repack_v(const float* __restrict__ V, uint32_t* __restrict__ H,
              uint32_t* __restrict__ L)
{
    __shared__ float SM[128][68];
    const int tid = threadIdx.x;
    const int bh = blockIdx.y, b = bh >> 3, h = bh & 7;
    const int k0 = blockIdx.x * 128;
    #pragma unroll
    for (int j = 0; j < 8; j++) {
        int idx = tid + j * 256;
        int r = idx >> 4, c4 = (idx & 15) * 4;
        *(float4*)&SM[r][c4] =
            *(const float4*)(V + (size_t)(b * 2048 + k0 + r) * 512 + h * 64 + c4);
    }
    __syncthreads();
    #pragma unroll
    for (int j = 0; j < 16; j++) {
        int idx = tid + j * 256;
        int d = idx >> 6, kp = idx & 63;
        uint32_t hh, ll;
        split_pair(SM[2 * kp][d], SM[2 * kp + 1][d], hh, ll);
        size_t dst = ((size_t)bh * 64 + d) * 1024 + k0 / 2 + kp;
        H[dst] = hh; L[dst] = ll;
    }
}

// ============================================================================
// gemm_cp: C[M,N] = A @ W (pre-packed bf16 hi/lo operands), cp.async
// double-buffered staging. BM=128, BN=128, BK=32; 256 thr, warp tile 32x64.
// Smem per buffer: Ah|Al|Bh|Bl each 128 rows x 20 words (2560 w); 2 buffers.
// mode 0: fp32 C (+bias). mode 1: packed qk out ([b,h][tok][dpair]).
// ============================================================================
#define GB 10240   // words per stage buffer

__global__ __launch_bounds__(256, 2)
void gemm_cp(const uint32_t* __restrict__ AH, const uint32_t* __restrict__ AL,
             const uint32_t* __restrict__ BH, const uint32_t* __restrict__ BL,
             float* __restrict__ C, uint32_t* __restrict__ OH,
             uint32_t* __restrict__ OL, const float* __restrict__ bias,
             int M, int N, int K, int mode)
{
    extern __shared__ uint32_t gs[];
    const uint32_t smb = smem_u32(gs);

    const int tid = threadIdx.x;
    const int lane = tid & 31, warp = tid >> 5;
    const int wm = warp & 3, wn = warp >> 2;
    const int g = lane >> 2, t = lane & 3;
    const int m0 = blockIdx.y * 128, n0 = blockIdx.x * 128;
    const int Kw = K >> 1;

    const int arow_sel = (lane & 7) + (lane & 8);
    const int acol_sel = (lane & 16) ? 4 : 0;
    const int brow_sel = lane & 7;
    const int bcol_sel = (lane & 8) ? 4 : 0;

    const int srow = tid >> 2, sseg = tid & 3;

    float acc[2][8][4];
    #pragma unroll
    for (int mt = 0; mt < 2; mt++)
        #pragma unroll
        for (int nt = 0; nt < 8; nt++)
            #pragma unroll
            for (int i = 0; i < 4; i++) acc[mt][nt][i] = 0.f;

    auto stage = [&](int buf, int k0) {
        const int base = buf * GB;
        #pragma unroll
        for (int j = 0; j < 2; j++) {
            const int row = srow + j * 64;
            const uint32_t sa = smb + (uint32_t)((base + row * 20 + sseg * 4) * 4);
            const size_t ga = (size_t)(m0 + row) * Kw + (k0 >> 1) + sseg * 4;
            cpa16(sa, AH + ga);
            cpa16(sa + 2560 * 4, AL + ga);
            const size_t gb = (size_t)(n0 + row) * Kw + (k0 >> 1) + sseg * 4;
            cpa16(sa + 5120 * 4, BH + gb);
            cpa16(sa + 7680 * 4, BL + gb);
        }
    };

    stage(0, 0);
    CP_COMMIT();

    int buf = 0;
    for (int k0 = 0; k0 < K; k0 += 32) {
        if (k0 + 32 < K) {
            stage(buf ^ 1, k0 + 32);
            CP_COMMIT();
            CP_WAIT1();
        } else {
            CP_WAIT0();
        }
        __syncthreads();

        const int base = buf * GB;
        #pragma unroll
        for (int s = 0; s < 2; s++) {
            uint32_t aH[2][4], aL[2][4];
            #pragma unroll
            for (int mt = 0; mt < 2; mt++) {
                const uint32_t aoff = smb +
                    (uint32_t)((base + (wm * 32 + mt * 16 + arow_sel) * 20 +
                                s * 8 + acol_sel) * 4);
                ldsm_x4(aH[mt], aoff);
                ldsm_x4(aL[mt], aoff + 2560 * 4);
            }
            #pragma unroll
            for (int nt = 0; nt < 8; nt++) {
                const uint32_t boff = smb +
                    (uint32_t)((base + (wn * 64 + nt * 8 + brow_sel) * 20 +
                                s * 8 + bcol_sel) * 4);
                uint32_t bH[2], bL[2];
                ldsm_x2(bH, boff + 5120 * 4);
                ldsm_x2(bL, boff + 7680 * 4);
                mmabf_x3(acc[0][nt], aH[0], aL[0], bH, bL);
                mmabf_x3(acc[1][nt], aH[1], aL[1], bH, bL);
            }
        }
        __syncthreads();
        buf ^= 1;
    }

    if (mode == 0) {
        #pragma unroll
        for (int mt = 0; mt < 2; mt++) {
            const int r0 = m0 + wm * 32 + mt * 16 + g;
            #pragma unroll
            for (int nt = 0; nt < 8; nt++) {
                const int c0 = n0 + wn * 64 + nt * 8 + t * 2;
                float2 v0 = make_float2(acc[mt][nt][0], acc[mt][nt][1]);
                float2 v1 = make_float2(acc[mt][nt][2], acc[mt][nt][3]);
                if (bias) {
                    float b0v = bias[c0], b1v = bias[c0 + 1];
                    v0.x += b0v; v0.y += b1v;
                    v1.x += b0v; v1.y += b1v;
                }
                *(float2*)(C + (size_t)r0 * N + c0) = v0;
                *(float2*)(C + (size_t)(r0 + 8) * N + c0) = v1;
            }
        }
    } else {
        // packed qk out: dst = ((b*8+h)*2048 + tok)*32 + (c0&63)/2
        #pragma unroll
        for (int mt = 0; mt < 2; mt++) {
            const int r0 = m0 + wm * 32 + mt * 16 + g;
            const int b = r0 >> 11;
            #pragma unroll
            for (int nt = 0; nt < 8; nt++) {
                const int c0 = n0 + wn * 64 + nt * 8 + t * 2;
                const int h = c0 >> 6, w = (c0 & 63) >> 1;
                uint32_t hh, ll;
                split_pair(acc[mt][nt][0], acc[mt][nt][1], hh, ll);
                size_t d0 = ((size_t)(b * 8 + h) * 2048 + (r0 & 2047)) * 32 + w;
                OH[d0] = hh; OL[d0] = ll;
                split_pair(acc[mt][nt][2], acc[mt][nt][3], hh, ll);
                size_t d1 = d0 + 8 * 32;
                OH[d1] = hh; OL[d1] = ll;
            }
        }
    }
}

// ============================================================================
// flash_cp: bf16 x3, P in registers, cp.async double-buffered K/V staging.
// Per CTA: 128 q, one (b,h). 256 thr = 8 warps, warp owns 16 q.
// Smem words: Qh[0..4607] Ql[4608..9215]; per buf (9216 + buf*9216):
//   Kh +0, Kl +2304, Vh +4608, Vl +6912 (each 64x36); msk ints at 27648+buf*64.
// ============================================================================
#define FL_KV    9216
#define FL_BUF   9216
#define FL_MSK   27648
#define FLASH_SMEM_BYTES ((FL_MSK + 2 * 64) * 4)   // 111104 B

__global__ __launch_bounds__(256, 2)
void flash_cp(const uint32_t* __restrict__ QHg, const uint32_t* __restrict__ QLg,
              const uint32_t* __restrict__ KHg, const uint32_t* __restrict__ KLg,
              const uint32_t* __restrict__ VHg, const uint32_t* __restrict__ VLg,
              const int* __restrict__ mask,
              uint32_t* __restrict__ OH, uint32_t* __restrict__ OL)
{
    extern __shared__ uint32_t fsm[];
    const uint32_t smb = smem_u32(fsm);

    const int bh = blockIdx.y;
    const int b = bh >> 3, h = bh & 7;
    const int q0 = blockIdx.x * 128;

    const int tid = threadIdx.x;
    const int lane = tid & 31, warp = tid >> 5;
    const int g = lane >> 2, t = lane & 3;
    const int pr = warp * 16;

    const int arow_sel = (lane & 7) + (lane & 8);
    const int acol_sel = (lane & 16) ? 4 : 0;
    const int brow_sel = lane & 7;
    const int bcol_sel = (lane & 8) ? 4 : 0;

    const int* mb = mask + (size_t)b * MK;

    // prologue: stage Q (128 rows x 8 segs, hi+lo) + tile 0 in group 0
    #pragma unroll
    for (int j = 0; j < 4; j++) {
        const int idx = tid + j * 256;
        const int row = idx >> 3, seg = idx & 7;
        const uint32_t sa = smb + (uint32_t)((row * 36 + seg * 4) * 4);
        const size_t gq = ((size_t)bh * 2048 + q0 + row) * 32 + seg * 4;
        cpa16(sa, QHg + gq);
        cpa16(sa + 4608 * 4, QLg + gq);
    }
    {
        const int row = tid >> 3, seg = tid & 7;       // 256 = 32 rows? no:
        // 512 (row,seg) pairs over 2 iterations
        #pragma unroll
        for (int j = 0; j < 2; j++) {
            const int idx = tid + j * 256;
            const int r = idx >> 3, sg = idx & 7;
            const uint32_t sa = smb + (uint32_t)((FL_KV + r * 36 + sg * 4) * 4);
            const size_t gk = ((size_t)bh * 2048 + r) * 32 + sg * 4;
            cpa16(sa, KHg + gk);
            cpa16(sa + 2304 * 4, KLg + gk);
            const size_t gv = ((size_t)bh * 64 + r) * 1024 + sg * 4;
            cpa16(sa + 4608 * 4, VHg + gv);
            cpa16(sa + 6912 * 4, VLg + gv);
        }
        if (tid < 16) {
            const uint32_t sa = smb + (uint32_t)((FL_MSK + tid * 4) * 4);
            cpa16(sa, mb + tid * 4);
        }
        (void)row; (void)seg;
    }
    CP_COMMIT();

    float of[8][4];
    #pragma unroll
    for (int nt = 0; nt < 8; nt++)
        #pragma unroll
        for (int i = 0; i < 4; i++) of[nt][i] = 0.f;
    float mrow0 = -3.0e38f, mrow1 = -3.0e38f, lrow0 = 0.f, lrow1 = 0.f;
    const float scale = 0.125f;

    int buf = 0;
    for (int kt = 0; kt < MK; kt += 64) {
        if (kt + 64 < MK) {
            const int nb = buf ^ 1;
            const int base = FL_KV + nb * FL_BUF;
            #pragma unroll
            for (int j = 0; j < 2; j++) {
                const int idx = tid + j * 256;
                const int r = idx >> 3, sg = idx & 7;
                const uint32_t sa = smb + (uint32_t)((base + r * 36 + sg * 4) * 4);
                const size_t gk = ((size_t)bh * 2048 + kt + 64 + r) * 32 + sg * 4;
                cpa16(sa, KHg + gk);
                cpa16(sa + 2304 * 4, KLg + gk);
                const size_t gv = ((size_t)bh * 64 + r) * 1024 + ((kt + 64) >> 1) + sg * 4;
                cpa16(sa + 4608 * 4, VHg + gv);
                cpa16(sa + 6912 * 4, VLg + gv);
            }
            if (tid < 16) {
                const uint32_t sa = smb + (uint32_t)((FL_MSK + nb * 64 + tid * 4) * 4);
                cpa16(sa, mb + kt + 64 + tid * 4);
            }
            CP_COMMIT();
            CP_WAIT1();
        } else {
            CP_WAIT0();
        }
        __syncthreads();

        const int base = FL_KV + buf * FL_BUF;
        const int* mi = (const int*)(fsm + FL_MSK + buf * 64);

        // ---- S = Q K^T ----
        float sf[8][4];
        #pragma unroll
        for (int nt = 0; nt < 8; nt++)
            #pragma unroll
            for (int i = 0; i < 4; i++) sf[nt][i] = 0.f;

        #pragma unroll
        for (int s = 0; s < 4; s++) {
            uint32_t aH[4], aL[4];
            const uint32_t qoff = smb +
                (uint32_t)(((pr + arow_sel) * 36 + s * 8 + acol_sel) * 4);
            ldsm_x4(aH, qoff);
            ldsm_x4(aL, qoff + 4608 * 4);
            #pragma unroll
            for (int nt = 0; nt < 8; nt++) {
                const uint32_t koff = smb +
                    (uint32_t)((base + (nt * 8 + brow_sel) * 36 + s * 8 + bcol_sel) * 4);
                uint32_t bH[2], bL[2];
                ldsm_x2(bH, koff);
                ldsm_x2(bL, koff + 2304 * 4);
                mmabf_x3(sf[nt], aH, aL, bH, bL);
            }
        }

        // ---- scale + mask + online softmax ----
        float mx0 = -3.0e38f, mx1 = -3.0e38f;
        #pragma unroll
        for (int nt = 0; nt < 8; nt++) {
            float mk0 = mi[nt * 8 + 2 * t]     ? 0.f : -1.0e30f;
            float mk1 = mi[nt * 8 + 2 * t + 1] ? 0.f : -1.0e30f;
            sf[nt][0] = sf[nt][0] * scale + mk0;
            sf[nt][1] = sf[nt][1] * scale + mk1;
            sf[nt][2] = sf[nt][2] * scale + mk0;
            sf[nt][3] = sf[nt][3] * scale + mk1;
            mx0 = fmaxf(mx0, fmaxf(sf[nt][0], sf[nt][1]));
            mx1 = fmaxf(mx1, fmaxf(sf[nt][2], sf[nt][3]));
        }
        mx0 = fmaxf(mx0, __shfl_xor_sync(0xffffffffu, mx0, 1));
        mx0 = fmaxf(mx0, __shfl_xor_sync(0xffffffffu, mx0, 2));
        mx1 = fmaxf(mx1, __shfl_xor_sync(0xffffffffu, mx1, 1));
        mx1 = fmaxf(mx1, __shfl_xor_sync(0xffffffffu, mx1, 2));

        const float mn0 = fmaxf(mrow0, mx0), mn1 = fmaxf(mrow1, mx1);
        const float corr0 = __expf(mrow0 - mn0), corr1 = __expf(mrow1 - mn1);
        float ls0 = 0.f, ls1 = 0.f;
        #pragma unroll
        for (int nt = 0; nt < 8; nt++) {
            sf[nt][0] = __expf(sf[nt][0] - mn0);
            sf[nt][1] = __expf(sf[nt][1] - mn0);
            sf[nt][2] = __expf(sf[nt][2] - mn1);
            sf[nt][3] = __expf(sf[nt][3] - mn1);
            ls0 += sf[nt][0] + sf[nt][1];
            ls1 += sf[nt][2] + sf[nt][3];
        }
        ls0 += __shfl_xor_sync(0xffffffffu, ls0, 1);
        ls0 += __shfl_xor_sync(0xffffffffu, ls0, 2);
        ls1 += __shfl_xor_sync(0xffffffffu, ls1, 1);
        ls1 += __shfl_xor_sync(0xffffffffu, ls1, 2);

        lrow0 = lrow0 * corr0 + ls0; mrow0 = mn0;
        lrow1 = lrow1 * corr1 + ls1; mrow1 = mn1;

        #pragma unroll
        for (int nt = 0; nt < 8; nt++) {
            of[nt][0] *= corr0; of[nt][1] *= corr0;
            of[nt][2] *= corr1; of[nt][3] *= corr1;
        }

        // ---- O += P @ V ----
        #pragma unroll
        for (int u = 0; u < 4; u++) {
            uint32_t pH[4], pL[4];
            split_pair(sf[2 * u][0],     sf[2 * u][1],     pH[0], pL[0]);
            split_pair(sf[2 * u][2],     sf[2 * u][3],     pH[1], pL[1]);
            split_pair(sf[2 * u + 1][0], sf[2 * u + 1][1], pH[2], pL[2]);
            split_pair(sf[2 * u + 1][2], sf[2 * u + 1][3], pH[3], pL[3]);
            #pragma unroll
            for (int nt = 0; nt < 8; nt++) {
                const uint32_t voff = smb +
                    (uint32_t)((base + (nt * 8 + brow_sel) * 36 + u * 8 + bcol_sel) * 4);
                uint32_t bH[2], bL[2];
                ldsm_x2(bH, voff + 4608 * 4);
                ldsm_x2(bL, voff + 6912 * 4);
                mmabf_x3(of[nt], pH, pL, bH, bL);
            }
        }
        __syncthreads();
        buf ^= 1;
    }

    // epilogue: packed hi/lo O out ([tok][INNER/2 words])
    const float inv0 = 1.f / lrow0, inv1 = 1.f / lrow1;
    const int qa = q0 + pr + g;
    const size_t ro0 = ((size_t)(b * 2048 + qa)) * 256;
    const size_t ro1 = ro0 + 8 * 256;
    #pragma unroll
    for (int nt = 0; nt < 8; nt++) {
        const int w = h * 32 + nt * 4 + t;
        uint32_t hh, ll;
        split_pair(of[nt][0] * inv0, of[nt][1] * inv0, hh, ll);
        OH[ro0 + w] = hh; OL[ro0 + w] = ll;
        split_pair(of[nt][2] * inv1, of[nt][3] * inv1, hh, ll);
        OH[ro1 + w] = hh; OL[ro1 + w] = ll;
    }
}

// ----------------------------------------------------------------------------
// kernel_launch
// Inputs: 0=x, 1=context, 2=mask (int32), 3=Wq, 4=Wk, 5=Wv, 6=Wo, 7=bo
// ----------------------------------------------------------------------------
extern "C" void kernel_launch(void* const* d_in, const int* in_sizes, int n_in,
                              void* d_out, int out_size)
{
    const float* x    = (const float*)d_in[0];
    const float* ctx  = (const float*)d_in[1];
    const int*   mask = (const int*)d_in[2];
    const float* Wq   = (const float*)d_in[3];
    const float* Wk   = (const float*)d_in[4];
    const float* Wv   = (const float*)d_in[5];
    const float* Wo   = (const float*)d_in[6];
    const float* bo   = (const float*)d_in[7];
    float* out = (float*)d_out;

    uint32_t *xH, *xL, *cH, *cL, *WqH, *WqL, *WkH, *WkL, *WvH, *WvL, *WoH, *WoL;
    uint32_t *QH, *QL, *KH, *KL, *VtH, *VtL, *OH2, *OL2;
    float *Vf;
    cudaGetSymbolAddress((void**)&xH, g_xH);   cudaGetSymbolAddress((void**)&xL, g_xL);
    cudaGetSymbolAddress((void**)&cH, g_cH);   cudaGetSymbolAddress((void**)&cL, g_cL);
    cudaGetSymbolAddress((void**)&WqH, g_WqH); cudaGetSymbolAddress((void**)&WqL, g_WqL);
    cudaGetSymbolAddress((void**)&WkH, g_WkH); cudaGetSymbolAddress((void**)&WkL, g_WkL);
    cudaGetSymbolAddress((void**)&WvH, g_WvH); cudaGetSymbolAddress((void**)&WvL, g_WvL);
    cudaGetSymbolAddress((void**)&WoH, g_WoH); cudaGetSymbolAddress((void**)&WoL, g_WoL);
    cudaGetSymbolAddress((void**)&QH, g_QH);   cudaGetSymbolAddress((void**)&QL, g_QL);
    cudaGetSymbolAddress((void**)&KH, g_KH);   cudaGetSymbolAddress((void**)&KL, g_KL);
    cudaGetSymbolAddress((void**)&VtH, g_VtH); cudaGetSymbolAddress((void**)&VtL, g_VtL);
    cudaGetSymbolAddress((void**)&OH2, g_OH2); cudaGetSymbolAddress((void**)&OL2, g_OL2);
    cudaGetSymbolAddress((void**)&Vf, g_Vf);

    cudaFuncSetAttribute(gemm_cp, cudaFuncAttributeMaxDynamicSharedMemorySize,
                         2 * GB * 4);
    cudaFuncSetAttribute(flash_cp, cudaFuncAttributeMaxDynamicSharedMemorySize,
                         FLASH_SMEM_BYTES);

    // repack inputs + weights
    repack_a<<<8192, 256>>>(x, xH, xL, 8192 * 1024 / 4);
    repack_a<<<8192, 256>>>(ctx, cH, cL, 8192 * 1024 / 4);
    repack_w<<<dim3(8, 8), 256>>>(Wq, WqH, WqL, 1024, 512);
    repack_w<<<dim3(8, 8), 256>>>(Wk, WkH, WkL, 1024, 512);
    repack_w<<<dim3(8, 8), 256>>>(Wv, WvH, WvL, 1024, 512);
    repack_w<<<dim3(4, 16), 256>>>(Wo, WoH, WoL, 512, 1024);

    // projections
    {
        dim3 gp(512 / 128, 8192 / 128);
        gemm_cp<<<gp, 256, 2 * GB * 4>>>(xH, xL, WqH, WqL, nullptr, QH, QL,
                                         nullptr, 8192, 512, 1024, 1);
        gemm_cp<<<gp, 256, 2 * GB * 4>>>(cH, cL, WkH, WkL, nullptr, KH, KL,
                                         nullptr, 8192, 512, 1024, 1);
        gemm_cp<<<gp, 256, 2 * GB * 4>>>(cH, cL, WvH, WvL, Vf, nullptr, nullptr,
                                         nullptr, 8192, 512, 1024, 0);
    }
    repack_v<<<dim3(16, 32), 256>>>(Vf, VtH, VtL);

    // flash attention
    {
        dim3 grid(NQ / 128, BSZ * HEADS);
        flash_cp<<<grid, 256, FLASH_SMEM_BYTES>>>(QH, QL, KH, KL, VtH, VtL,
                                                  mask, OH2, OL2);
    }
    // out = O @ Wo + bo
    {
        dim3 go(1024 / 128, 8192 / 128);
        gemm_cp<<<go, 256, 2 * GB * 4>>>(OH2, OL2, WoH, WoL, out, nullptr,
                                         nullptr, bo, 8192, 1024, 512, 0);
    }
}

// round 10
// speedup vs baseline: 3.0192x; 1.2459x over previous
#include <cuda_runtime.h>
#include <math.h>
#include <stdint.h>

// Problem constants
#define BSZ   4
#define NQ    2048
#define MK    2048
#define DIMX  1024
#define CTXD  1024
#define HEADS 8
#define DHEAD 64
#define INNER 512   // HEADS * DHEAD

// ============================================================================
// Packed bf16 hi/lo scratch in gmem (allocation-free: __device__ globals)
// ============================================================================
__device__ uint32_t g_xH[(size_t)8192 * 512], g_xL[(size_t)8192 * 512];
__device__ uint32_t g_cH[(size_t)8192 * 512], g_cL[(size_t)8192 * 512];
__device__ uint32_t g_WqH[512 * 512],  g_WqL[512 * 512];
__device__ uint32_t g_WkH[512 * 512],  g_WkL[512 * 512];
__device__ uint32_t g_WvH[512 * 512],  g_WvL[512 * 512];
__device__ uint32_t g_WoH[1024 * 256], g_WoL[1024 * 256];
__device__ uint32_t g_QH[(size_t)32 * 2048 * 32], g_QL[(size_t)32 * 2048 * 32];
__device__ uint32_t g_KH[(size_t)32 * 2048 * 32], g_KL[(size_t)32 * 2048 * 32];
__device__ uint32_t g_VtH[(size_t)32 * 64 * 1024], g_VtL[(size_t)32 * 64 * 1024];
__device__ float    g_Vf[(size_t)8192 * 512];
__device__ uint32_t g_OH2[(size_t)8192 * 256], g_OL2[(size_t)8192 * 256];
__device__ int      g_idx[BSZ * MK];
__device__ int      g_cnt[BSZ];

// ============================================================================
// bf16 x3 helpers, ldmatrix, cp.async
// ============================================================================
__device__ __forceinline__ uint32_t pack_bf16x2(float e0, float e1) {
    uint32_t r;
    asm("cvt.rn.bf16x2.f32 %0, %1, %2;" : "=r"(r) : "f"(e1), "f"(e0));
    return r;
}
__device__ __forceinline__ void split_pair(float x0, float x1,
                                           uint32_t& hi, uint32_t& lo) {
    hi = pack_bf16x2(x0, x1);
    float h0 = __uint_as_float(hi << 16);
    float h1 = __uint_as_float(hi & 0xffff0000u);
    lo = pack_bf16x2(x0 - h0, x1 - h1);
}
__device__ __forceinline__ void mmabf(float c[4], const uint32_t a[4],
                                      const uint32_t b[2]) {
    asm volatile(
        "mma.sync.aligned.m16n8k16.row.col.f32.bf16.bf16.f32 "
        "{%0,%1,%2,%3},{%4,%5,%6,%7},{%8,%9},{%0,%1,%2,%3};"
        : "+f"(c[0]), "+f"(c[1]), "+f"(c[2]), "+f"(c[3])
        : "r"(a[0]), "r"(a[1]), "r"(a[2]), "r"(a[3]), "r"(b[0]), "r"(b[1]));
}
__device__ __forceinline__ void mmabf_x3(float c[4],
                                         const uint32_t aH[4], const uint32_t aL[4],
                                         const uint32_t bH[2], const uint32_t bL[2]) {
    mmabf(c, aH, bH);
    mmabf(c, aH, bL);
    mmabf(c, aL, bH);
}
__device__ __forceinline__ void ldsm_x4(uint32_t* r, uint32_t a) {
    asm volatile("ldmatrix.sync.aligned.m8n8.x4.shared.b16 {%0,%1,%2,%3}, [%4];"
                 : "=r"(r[0]), "=r"(r[1]), "=r"(r[2]), "=r"(r[3]) : "r"(a));
}
__device__ __forceinline__ void ldsm_x2(uint32_t* r, uint32_t a) {
    asm volatile("ldmatrix.sync.aligned.m8n8.x2.shared.b16 {%0,%1}, [%2];"
                 : "=r"(r[0]), "=r"(r[1]) : "r"(a));
}
__device__ __forceinline__ uint32_t smem_u32(const void* p) {
    uint32_t a;
    asm("{ .reg .u64 t; cvta.to.shared.u64 t, %1; cvt.u32.u64 %0, t; }"
        : "=r"(a) : "l"(p));
    return a;
}
__device__ __forceinline__ void cpa16(uint32_t sa, const void* g) {
    asm volatile("cp.async.cg.shared.global [%0], [%1], 16;"
                 :: "r"(sa), "l"(g) : "memory");
}
// predicated: invalid -> zero-fill 16 bytes (src not accessed)
__device__ __forceinline__ void cpa16z(uint32_t sa, const void* g, bool valid) {
    int sz = valid ? 16 : 0;
    asm volatile("cp.async.cg.shared.global [%0], [%1], 16, %2;"
                 :: "r"(sa), "l"(g), "r"(sz) : "memory");
}
#define CP_COMMIT() asm volatile("cp.async.commit_group;" ::: "memory")
#define CP_WAIT1()  asm volatile("cp.async.wait_group 1;"  ::: "memory")
#define CP_WAIT0()  asm volatile("cp.async.wait_group 0;"  ::: "memory")

// ============================================================================
// compact_mask: per batch, indices of mask!=0 (order-preserving) + count.
// 1 block/batch, 256 threads x 8 elems.
// ============================================================================
__global__ __launch_bounds__(256)
void compact_mask(const int* __restrict__ mask, int* __restrict__ idxOut,
                  int* __restrict__ cntOut)
{
    __shared__ int warp_sums[8];
    const int b = blockIdx.x;
    const int tid = threadIdx.x;
    const int lane = tid & 31, w = tid >> 5;
    const int* mb = mask + b * MK;

    int loc[8], c = 0;
    #pragma unroll
    for (int j = 0; j < 8; j++) {
        loc[j] = (mb[tid * 8 + j] != 0);
        c += loc[j];
    }
    int pre = c;
    #pragma unroll
    for (int off = 1; off < 32; off <<= 1) {
        int v = __shfl_up_sync(0xffffffffu, pre, off);
        if (lane >= off) pre += v;
    }
    if (lane == 31) warp_sums[w] = pre;
    __syncthreads();
    if (tid == 0) {
        int s = 0;
        #pragma unroll
        for (int i = 0; i < 8; i++) { int t = warp_sums[i]; warp_sums[i] = s; s += t; }
        cntOut[b] = s;
    }
    __syncthreads();
    int start = warp_sums[w] + pre - c;
    #pragma unroll
    for (int j = 0; j < 8; j++)
        if (loc[j]) idxOut[b * MK + start++] = tid * 8 + j;
}

// ============================================================================
// repack_a: fp32 [R][K] -> packed hi/lo words [R][K/2] (flat)
// ============================================================================
__global__ __launch_bounds__(256)
void repack_a(const float* __restrict__ A, uint32_t* __restrict__ H,
              uint32_t* __restrict__ L, int n4)
{
    int i = blockIdx.x * 256 + threadIdx.x;
    if (i >= n4) return;
    float4 a = ((const float4*)A)[i];
    uint32_t h0, l0, h1, l1;
    split_pair(a.x, a.y, h0, l0);
    split_pair(a.z, a.w, h1, l1);
    H[2 * i] = h0; H[2 * i + 1] = h1;
    L[2 * i] = l0; L[2 * i + 1] = l1;
}

// ============================================================================
// repack_w: fp32 W[K][N] -> transposed packed [N][K/2]. grid (K/128, N/64).
// ============================================================================
__global__ __launch_bounds__(256)
void repack_w(const float* __restrict__ W, uint32_t* __restrict__ H,
              uint32_t* __restrict__ L, int K, int N)
{
    __shared__ float SM[128][68];
    const int tid = threadIdx.x;
    const int k0 = blockIdx.x * 128, n0 = blockIdx.y * 64;
    #pragma unroll
    for (int j = 0; j < 8; j++) {
        int idx = tid + j * 256;
        int r = idx >> 4, c4 = (idx & 15) * 4;
        *(float4*)&SM[r][c4] = *(const float4*)(W + (size_t)(k0 + r) * N + n0 + c4);
    }
    __syncthreads();
    #pragma unroll
    for (int j = 0; j < 16; j++) {
        int idx = tid + j * 256;
        int n = idx >> 6, kp = idx & 63;
        uint32_t h, l;
        split_pair(SM[2 * kp][n], SM[2 * kp + 1][n], h, l);
        size_t d = (size_t)(n0 + n) * (K / 2) + k0 / 2 + kp;
        H[d] = h; L[d] = l;
    }
}

// ============================================================================
// repack_v (with key gather/compaction):
// fp32 V [B*2048][512] -> per-(b,h) transposed packed [64 d][1024 keypair],
// keys reordered by idx, zero-filled past cnt. grid (2048/128, 32)
// ============================================================================
__global__ __launch_bounds__(256)
void repack_v(const float* __restrict__ V, uint32_t* __restrict__ H,
              uint32_t* __restrict__ L, const int* __restrict__ idx,
              const int* __restrict__ cnt)
{
    __shared__ float SM[128][68];
    const int tid = threadIdx.x;
    const int bh = blockIdx.y, b = bh >> 3, h = bh & 7;
    const int k0 = blockIdx.x * 128;
    const int cntb = cnt[b];
    #pragma unroll
    for (int j = 0; j < 8; j++) {
        int i2 = tid + j * 256;
        int r = i2 >> 4, c4 = (i2 & 15) * 4;
        float4 v = make_float4(0.f, 0.f, 0.f, 0.f);
        const int tok_i = k0 + r;
        if (tok_i < cntb) {
            const int tok = idx[b * MK + tok_i];
            v = *(const float4*)(V + (size_t)(b * 2048 + tok) * 512 + h * 64 + c4);
        }
        *(float4*)&SM[r][c4] = v;
    }
    __syncthreads();
    #pragma unroll
    for (int j = 0; j < 16; j++) {
        int i2 = tid + j * 256;
        int d = i2 >> 6, kp = i2 & 63;
        uint32_t hh, ll;
        split_pair(SM[2 * kp][d], SM[2 * kp + 1][d], hh, ll);
        size_t dst = ((size_t)bh * 64 + d) * 1024 + k0 / 2 + kp;
        H[dst] = hh; L[dst] = ll;
    }
}

// ============================================================================
// gemm_cp: C[M,N] = A @ W (pre-packed bf16 hi/lo), cp.async double-buffered.
// BM=128, BN=128, BK=32; 256 thr, warp tile 32x64.
// mode 0: fp32 C (+bias). mode 1: packed qk out ([b,h][tok][dpair]).
// ============================================================================
#define GB 10240   // words per stage buffer

__global__ __launch_bounds__(256, 2)
void gemm_cp(const uint32_t* __restrict__ AH, const uint32_t* __restrict__ AL,
             const uint32_t* __restrict__ BH, const uint32_t* __restrict__ BL,
             float* __restrict__ C, uint32_t* __restrict__ OH,
             uint32_t* __restrict__ OL, const float* __restrict__ bias,
             int M, int N, int K, int mode)
{
    extern __shared__ uint32_t gs[];
    const uint32_t smb = smem_u32(gs);

    const int tid = threadIdx.x;
    const int lane = tid & 31, warp = tid >> 5;
    const int wm = warp & 3, wn = warp >> 2;
    const int g = lane >> 2, t = lane & 3;
    const int m0 = blockIdx.y * 128, n0 = blockIdx.x * 128;
    const int Kw = K >> 1;

    const int arow_sel = (lane & 7) + (lane & 8);
    const int acol_sel = (lane & 16) ? 4 : 0;
    const int brow_sel = lane & 7;
    const int bcol_sel = (lane & 8) ? 4 : 0;

    const int srow = tid >> 2, sseg = tid & 3;

    float acc[2][8][4];
    #pragma unroll
    for (int mt = 0; mt < 2; mt++)
        #pragma unroll
        for (int nt = 0; nt < 8; nt++)
            #pragma unroll
            for (int i = 0; i < 4; i++) acc[mt][nt][i] = 0.f;

    auto stage = [&](int buf, int k0) {
        const int base = buf * GB;
        #pragma unroll
        for (int j = 0; j < 2; j++) {
            const int row = srow + j * 64;
            const uint32_t sa = smb + (uint32_t)((base + row * 20 + sseg * 4) * 4);
            const size_t ga = (size_t)(m0 + row) * Kw + (k0 >> 1) + sseg * 4;
            cpa16(sa, AH + ga);
            cpa16(sa + 2560 * 4, AL + ga);
            const size_t gb = (size_t)(n0 + row) * Kw + (k0 >> 1) + sseg * 4;
            cpa16(sa + 5120 * 4, BH + gb);
            cpa16(sa + 7680 * 4, BL + gb);
        }
    };

    stage(0, 0);
    CP_COMMIT();

    int buf = 0;
    for (int k0 = 0; k0 < K; k0 += 32) {
        if (k0 + 32 < K) {
            stage(buf ^ 1, k0 + 32);
            CP_COMMIT();
            CP_WAIT1();
        } else {
            CP_WAIT0();
        }
        __syncthreads();

        const int base = buf * GB;
        #pragma unroll
        for (int s = 0; s < 2; s++) {
            uint32_t aH[2][4], aL[2][4];
            #pragma unroll
            for (int mt = 0; mt < 2; mt++) {
                const uint32_t aoff = smb +
                    (uint32_t)((base + (wm * 32 + mt * 16 + arow_sel) * 20 +
                                s * 8 + acol_sel) * 4);
                ldsm_x4(aH[mt], aoff);
                ldsm_x4(aL[mt], aoff + 2560 * 4);
            }
            #pragma unroll
            for (int nt = 0; nt < 8; nt++) {
                const uint32_t boff = smb +
                    (uint32_t)((base + (wn * 64 + nt * 8 + brow_sel) * 20 +
                                s * 8 + bcol_sel) * 4);
                uint32_t bH[2], bL[2];
                ldsm_x2(bH, boff + 5120 * 4);
                ldsm_x2(bL, boff + 7680 * 4);
                mmabf_x3(acc[0][nt], aH[0], aL[0], bH, bL);
                mmabf_x3(acc[1][nt], aH[1], aL[1], bH, bL);
            }
        }
        __syncthreads();
        buf ^= 1;
    }

    if (mode == 0) {
        #pragma unroll
        for (int mt = 0; mt < 2; mt++) {
            const int r0 = m0 + wm * 32 + mt * 16 + g;
            #pragma unroll
            for (int nt = 0; nt < 8; nt++) {
                const int c0 = n0 + wn * 64 + nt * 8 + t * 2;
                float2 v0 = make_float2(acc[mt][nt][0], acc[mt][nt][1]);
                float2 v1 = make_float2(acc[mt][nt][2], acc[mt][nt][3]);
                if (bias) {
                    float b0v = bias[c0], b1v = bias[c0 + 1];
                    v0.x += b0v; v0.y += b1v;
                    v1.x += b0v; v1.y += b1v;
                }
                *(float2*)(C + (size_t)r0 * N + c0) = v0;
                *(float2*)(C + (size_t)(r0 + 8) * N + c0) = v1;
            }
        }
    } else {
        #pragma unroll
        for (int mt = 0; mt < 2; mt++) {
            const int r0 = m0 + wm * 32 + mt * 16 + g;
            const int b = r0 >> 11;
            #pragma unroll
            for (int nt = 0; nt < 8; nt++) {
                const int c0 = n0 + wn * 64 + nt * 8 + t * 2;
                const int h = c0 >> 6, w = (c0 & 63) >> 1;
                uint32_t hh, ll;
                split_pair(acc[mt][nt][0], acc[mt][nt][1], hh, ll);
                size_t d0 = ((size_t)(b * 8 + h) * 2048 + (r0 & 2047)) * 32 + w;
                OH[d0] = hh; OL[d0] = ll;
                split_pair(acc[mt][nt][2], acc[mt][nt][3], hh, ll);
                size_t d1 = d0 + 8 * 32;
                OH[d1] = hh; OL[d1] = ll;
            }
        }
    }
}

// ============================================================================
// flash_cp: bf16 x3, P in registers, cp.async double-buffered, COMPACTED keys.
// Per CTA: 128 q, one (b,h). K rows gathered via idx (zero-fill past cnt);
// V already compacted by repack_v. Loop bound Mp = ceil(cnt/64)*64.
// Validity replaces the mask: key column kt+c valid iff kt+c < cnt.
// ============================================================================
#define FL_KV    9216
#define FL_BUF   9216
#define FLASH_SMEM_BYTES ((FL_KV + 2 * FL_BUF) * 4)

__global__ __launch_bounds__(256, 2)
void flash_cp(const uint32_t* __restrict__ QHg, const uint32_t* __restrict__ QLg,
              const uint32_t* __restrict__ KHg, const uint32_t* __restrict__ KLg,
              const uint32_t* __restrict__ VHg, const uint32_t* __restrict__ VLg,
              const int* __restrict__ idx, const int* __restrict__ cnt,
              uint32_t* __restrict__ OH, uint32_t* __restrict__ OL)
{
    extern __shared__ uint32_t fsm[];
    const uint32_t smb = smem_u32(fsm);

    const int bh = blockIdx.y;
    const int b = bh >> 3, h = bh & 7;
    const int q0 = blockIdx.x * 128;

    const int tid = threadIdx.x;
    const int lane = tid & 31, warp = tid >> 5;
    const int g = lane >> 2, t = lane & 3;
    const int pr = warp * 16;

    const int arow_sel = (lane & 7) + (lane & 8);
    const int acol_sel = (lane & 16) ? 4 : 0;
    const int brow_sel = lane & 7;
    const int bcol_sel = (lane & 8) ? 4 : 0;

    const int cntb = cnt[b];
    const int Mp = (cntb + 63) & ~63;
    const int* gidx = idx + b * MK;

    auto stageKV = [&](int nb, int kt2) {
        const int base = FL_KV + nb * FL_BUF;
        #pragma unroll
        for (int j = 0; j < 2; j++) {
            const int i2 = tid + j * 256;
            const int r = i2 >> 3, sg = i2 & 7;
            const int tok_i = kt2 + r;
            const bool valid = tok_i < cntb;
            const int tok = valid ? gidx[tok_i] : 0;
            const uint32_t sa = smb + (uint32_t)((base + r * 36 + sg * 4) * 4);
            const size_t gk = ((size_t)bh * 2048 + tok) * 32 + sg * 4;
            cpa16z(sa, KHg + gk, valid);
            cpa16z(sa + 2304 * 4, KLg + gk, valid);
            const size_t gv = ((size_t)bh * 64 + r) * 1024 + (kt2 >> 1) + sg * 4;
            cpa16(sa + 4608 * 4, VHg + gv);
            cpa16(sa + 6912 * 4, VLg + gv);
        }
    };

    // prologue: stage Q + tile 0
    #pragma unroll
    for (int j = 0; j < 4; j++) {
        const int i2 = tid + j * 256;
        const int row = i2 >> 3, seg = i2 & 7;
        const uint32_t sa = smb + (uint32_t)((row * 36 + seg * 4) * 4);
        const size_t gq = ((size_t)bh * 2048 + q0 + row) * 32 + seg * 4;
        cpa16(sa, QHg + gq);
        cpa16(sa + 4608 * 4, QLg + gq);
    }
    stageKV(0, 0);
    CP_COMMIT();

    float of[8][4];
    #pragma unroll
    for (int nt = 0; nt < 8; nt++)
        #pragma unroll
        for (int i = 0; i < 4; i++) of[nt][i] = 0.f;
    float mrow0 = -3.0e38f, mrow1 = -3.0e38f, lrow0 = 0.f, lrow1 = 0.f;
    const float scale = 0.125f;

    int buf = 0;
    for (int kt = 0; kt < Mp; kt += 64) {
        if (kt + 64 < Mp) {
            stageKV(buf ^ 1, kt + 64);
            CP_COMMIT();
            CP_WAIT1();
        } else {
            CP_WAIT0();
        }
        __syncthreads();

        const int base = FL_KV + buf * FL_BUF;
        const int limit = cntb - kt;   // valid key columns in this tile

        // ---- S = Q K^T ----
        float sf[8][4];
        #pragma unroll
        for (int nt = 0; nt < 8; nt++)
            #pragma unroll
            for (int i = 0; i < 4; i++) sf[nt][i] = 0.f;

        #pragma unroll
        for (int s = 0; s < 4; s++) {
            uint32_t aH[4], aL[4];
            const uint32_t qoff = smb +
                (uint32_t)(((pr + arow_sel) * 36 + s * 8 + acol_sel) * 4);
            ldsm_x4(aH, qoff);
            ldsm_x4(aL, qoff + 4608 * 4);
            #pragma unroll
            for (int nt = 0; nt < 8; nt++) {
                const uint32_t koff = smb +
                    (uint32_t)((base + (nt * 8 + brow_sel) * 36 + s * 8 + bcol_sel) * 4);
                uint32_t bH[2], bL[2];
                ldsm_x2(bH, koff);
                ldsm_x2(bL, koff + 2304 * 4);
                mmabf_x3(sf[nt], aH, aL, bH, bL);
            }
        }

        // ---- scale + validity + online softmax ----
        float mx0 = -3.0e38f, mx1 = -3.0e38f;
        #pragma unroll
        for (int nt = 0; nt < 8; nt++) {
            const int c0 = nt * 8 + 2 * t;
            float mk0 = (c0     < limit) ? 0.f : -1.0e30f;
            float mk1 = (c0 + 1 < limit) ? 0.f : -1.0e30f;
            sf[nt][0] = sf[nt][0] * scale + mk0;
            sf[nt][1] = sf[nt][1] * scale + mk1;
            sf[nt][2] = sf[nt][2] * scale + mk0;
            sf[nt][3] = sf[nt][3] * scale + mk1;
            mx0 = fmaxf(mx0, fmaxf(sf[nt][0], sf[nt][1]));
            mx1 = fmaxf(mx1, fmaxf(sf[nt][2], sf[nt][3]));
        }
        mx0 = fmaxf(mx0, __shfl_xor_sync(0xffffffffu, mx0, 1));
        mx0 = fmaxf(mx0, __shfl_xor_sync(0xffffffffu, mx0, 2));
        mx1 = fmaxf(mx1, __shfl_xor_sync(0xffffffffu, mx1, 1));
        mx1 = fmaxf(mx1, __shfl_xor_sync(0xffffffffu, mx1, 2));

        const float mn0 = fmaxf(mrow0, mx0), mn1 = fmaxf(mrow1, mx1);
        const float corr0 = __expf(mrow0 - mn0), corr1 = __expf(mrow1 - mn1);
        float ls0 = 0.f, ls1 = 0.f;
        #pragma unroll
        for (int nt = 0; nt < 8; nt++) {
            sf[nt][0] = __expf(sf[nt][0] - mn0);
            sf[nt][1] = __expf(sf[nt][1] - mn0);
            sf[nt][2] = __expf(sf[nt][2] - mn1);
            sf[nt][3] = __expf(sf[nt][3] - mn1);
            ls0 += sf[nt][0] + sf[nt][1];
            ls1 += sf[nt][2] + sf[nt][3];
        }
        ls0 += __shfl_xor_sync(0xffffffffu, ls0, 1);
        ls0 += __shfl_xor_sync(0xffffffffu, ls0, 2);
        ls1 += __shfl_xor_sync(0xffffffffu, ls1, 1);
        ls1 += __shfl_xor_sync(0xffffffffu, ls1, 2);

        lrow0 = lrow0 * corr0 + ls0; mrow0 = mn0;
        lrow1 = lrow1 * corr1 + ls1; mrow1 = mn1;

        #pragma unroll
        for (int nt = 0; nt < 8; nt++) {
            of[nt][0] *= corr0; of[nt][1] *= corr0;
            of[nt][2] *= corr1; of[nt][3] *= corr1;
        }

        // ---- O += P @ V ----
        #pragma unroll
        for (int u = 0; u < 4; u++) {
            uint32_t pH[4], pL[4];
            split_pair(sf[2 * u][0],     sf[2 * u][1],     pH[0], pL[0]);
            split_pair(sf[2 * u][2],     sf[2 * u][3],     pH[1], pL[1]);
            split_pair(sf[2 * u + 1][0], sf[2 * u + 1][1], pH[2], pL[2]);
            split_pair(sf[2 * u + 1][2], sf[2 * u + 1][3], pH[3], pL[3]);
            #pragma unroll
            for (int nt = 0; nt < 8; nt++) {
                const uint32_t voff = smb +
                    (uint32_t)((base + (nt * 8 + brow_sel) * 36 + u * 8 + bcol_sel) * 4);
                uint32_t bH[2], bL[2];
                ldsm_x2(bH, voff + 4608 * 4);
                ldsm_x2(bL, voff + 6912 * 4);
                mmabf_x3(of[nt], pH, pL, bH, bL);
            }
        }
        __syncthreads();
        buf ^= 1;
    }

    // epilogue: packed hi/lo O out ([tok][INNER/2 words])
    const float inv0 = 1.f / lrow0, inv1 = 1.f / lrow1;
    const int qa = q0 + pr + g;
    const size_t ro0 = ((size_t)(b * 2048 + qa)) * 256;
    const size_t ro1 = ro0 + 8 * 256;
    #pragma unroll
    for (int nt = 0; nt < 8; nt++) {
        const int w = h * 32 + nt * 4 + t;
        uint32_t hh, ll;
        split_pair(of[nt][0] * inv0, of[nt][1] * inv0, hh, ll);
        OH[ro0 + w] = hh; OL[ro0 + w] = ll;
        split_pair(of[nt][2] * inv1, of[nt][3] * inv1, hh, ll);
        OH[ro1 + w] = hh; OL[ro1 + w] = ll;
    }
}

// ----------------------------------------------------------------------------
// kernel_launch
// Inputs: 0=x, 1=context, 2=mask (int32), 3=Wq, 4=Wk, 5=Wv, 6=Wo, 7=bo
// ----------------------------------------------------------------------------
extern "C" void kernel_launch(void* const* d_in, const int* in_sizes, int n_in,
                              void* d_out, int out_size)
{
    const float* x    = (const float*)d_in[0];
    const float* ctx  = (const float*)d_in[1];
    const int*   mask = (const int*)d_in[2];
    const float* Wq   = (const float*)d_in[3];
    const float* Wk   = (const float*)d_in[4];
    const float* Wv   = (const float*)d_in[5];
    const float* Wo   = (const float*)d_in[6];
    const float* bo   = (const float*)d_in[7];
    float* out = (float*)d_out;

    uint32_t *xH, *xL, *cH, *cL, *WqH, *WqL, *WkH, *WkL, *WvH, *WvL, *WoH, *WoL;
    uint32_t *QH, *QL, *KH, *KL, *VtH, *VtL, *OH2, *OL2;
    float *Vf;
    int *pidx, *pcnt;
    cudaGetSymbolAddress((void**)&xH, g_xH);   cudaGetSymbolAddress((void**)&xL, g_xL);
    cudaGetSymbolAddress((void**)&cH, g_cH);   cudaGetSymbolAddress((void**)&cL, g_cL);
    cudaGetSymbolAddress((void**)&WqH, g_WqH); cudaGetSymbolAddress((void**)&WqL, g_WqL);
    cudaGetSymbolAddress((void**)&WkH, g_WkH); cudaGetSymbolAddress((void**)&WkL, g_WkL);
    cudaGetSymbolAddress((void**)&WvH, g_WvH); cudaGetSymbolAddress((void**)&WvL, g_WvL);
    cudaGetSymbolAddress((void**)&WoH, g_WoH); cudaGetSymbolAddress((void**)&WoL, g_WoL);
    cudaGetSymbolAddress((void**)&QH, g_QH);   cudaGetSymbolAddress((void**)&QL, g_QL);
    cudaGetSymbolAddress((void**)&KH, g_KH);   cudaGetSymbolAddress((void**)&KL, g_KL);
    cudaGetSymbolAddress((void**)&VtH, g_VtH); cudaGetSymbolAddress((void**)&VtL, g_VtL);
    cudaGetSymbolAddress((void**)&OH2, g_OH2); cudaGetSymbolAddress((void**)&OL2, g_OL2);
    cudaGetSymbolAddress((void**)&Vf, g_Vf);
    cudaGetSymbolAddress((void**)&pidx, g_idx);
    cudaGetSymbolAddress((void**)&pcnt, g_cnt);

    cudaFuncSetAttribute(gemm_cp, cudaFuncAttributeMaxDynamicSharedMemorySize,
                         2 * GB * 4);
    cudaFuncSetAttribute(flash_cp, cudaFuncAttributeMaxDynamicSharedMemorySize,
                         FLASH_SMEM_BYTES);

    // mask compaction + repacks
    compact_mask<<<BSZ, 256>>>(mask, pidx, pcnt);
    repack_a<<<8192, 256>>>(x, xH, xL, 8192 * 1024 / 4);
    repack_a<<<8192, 256>>>(ctx, cH, cL, 8192 * 1024 / 4);
    repack_w<<<dim3(8, 8), 256>>>(Wq, WqH, WqL, 1024, 512);
    repack_w<<<dim3(8, 8), 256>>>(Wk, WkH, WkL, 1024, 512);
    repack_w<<<dim3(8, 8), 256>>>(Wv, WvH, WvL, 1024, 512);
    repack_w<<<dim3(4, 16), 256>>>(Wo, WoH, WoL, 512, 1024);

    // projections
    {
        dim3 gp(512 / 128, 8192 / 128);
        gemm_cp<<<gp, 256, 2 * GB * 4>>>(xH, xL, WqH, WqL, nullptr, QH, QL,
                                         nullptr, 8192, 512, 1024, 1);
        gemm_cp<<<gp, 256, 2 * GB * 4>>>(cH, cL, WkH, WkL, nullptr, KH, KL,
                                         nullptr, 8192, 512, 1024, 1);
        gemm_cp<<<gp, 256, 2 * GB * 4>>>(cH, cL, WvH, WvL, Vf, nullptr, nullptr,
                                         nullptr, 8192, 512, 1024, 0);
    }
    repack_v<<<dim3(16, 32), 256>>>(Vf, VtH, VtL, pidx, pcnt);

    // flash attention over compacted keys
    {
        dim3 grid(NQ / 128, BSZ * HEADS);
        flash_cp<<<grid, 256, FLASH_SMEM_BYTES>>>(QH, QL, KH, KL, VtH, VtL,
                                                  pidx, pcnt, OH2, OL2);
    }
    // out = O @ Wo + bo
    {
        dim3 go(1024 / 128, 8192 / 128);
        gemm_cp<<<go, 256, 2 * GB * 4>>>(OH2, OL2, WoH, WoL, out, nullptr,
                                         nullptr, bo, 8192, 1024, 512, 0);
    }
}

// round 14
// speedup vs baseline: 3.1031x; 1.0278x over previous
#include <cuda_runtime.h>
#include <math.h>
#include <stdint.h>

// Problem constants
#define BSZ   4
#define NQ    2048
#define MK    2048
#define DIMX  1024
#define CTXD  1024
#define HEADS 8
#define DHEAD 64
#define INNER 512   // HEADS * DHEAD

// ============================================================================
// Packed bf16 hi/lo scratch in gmem (allocation-free: __device__ globals)
// ============================================================================
__device__ uint32_t g_xH[(size_t)8192 * 512], g_xL[(size_t)8192 * 512];
__device__ uint32_t g_cH[(size_t)8192 * 512], g_cL[(size_t)8192 * 512];
__device__ uint32_t g_WqH[512 * 512],  g_WqL[512 * 512];
__device__ uint32_t g_WkH[512 * 512],  g_WkL[512 * 512];
__device__ uint32_t g_WvH[512 * 512],  g_WvL[512 * 512];
__device__ uint32_t g_WoH[1024 * 256], g_WoL[1024 * 256];
__device__ uint32_t g_QH[(size_t)32 * 2048 * 32], g_QL[(size_t)32 * 2048 * 32];
__device__ uint32_t g_KH[(size_t)32 * 2048 * 32], g_KL[(size_t)32 * 2048 * 32];
__device__ uint32_t g_VtH[(size_t)32 * 64 * 1024], g_VtL[(size_t)32 * 64 * 1024];
__device__ float    g_Vf[(size_t)8192 * 512];
__device__ uint32_t g_OH2[(size_t)8192 * 256], g_OL2[(size_t)8192 * 256];
__device__ int      g_idx[BSZ * MK];
__device__ int      g_cnt[BSZ];

// ============================================================================
// bf16 x3 helpers, ldmatrix, cp.async
// ============================================================================
__device__ __forceinline__ uint32_t pack_bf16x2(float e0, float e1) {
    uint32_t r;
    asm("cvt.rn.bf16x2.f32 %0, %1, %2;" : "=r"(r) : "f"(e1), "f"(e0));
    return r;
}
__device__ __forceinline__ void split_pair(float x0, float x1,
                                           uint32_t& hi, uint32_t& lo) {
    hi = pack_bf16x2(x0, x1);
    float h0 = __uint_as_float(hi << 16);
    float h1 = __uint_as_float(hi & 0xffff0000u);
    lo = pack_bf16x2(x0 - h0, x1 - h1);
}
__device__ __forceinline__ void mmabf(float c[4], const uint32_t a[4],
                                      const uint32_t b[2]) {
    asm volatile(
        "mma.sync.aligned.m16n8k16.row.col.f32.bf16.bf16.f32 "
        "{%0,%1,%2,%3},{%4,%5,%6,%7},{%8,%9},{%0,%1,%2,%3};"
        : "+f"(c[0]), "+f"(c[1]), "+f"(c[2]), "+f"(c[3])
        : "r"(a[0]), "r"(a[1]), "r"(a[2]), "r"(a[3]), "r"(b[0]), "r"(b[1]));
}
__device__ __forceinline__ void mmabf_x3(float c[4],
                                         const uint32_t aH[4], const uint32_t aL[4],
                                         const uint32_t bH[2], const uint32_t bL[2]) {
    mmabf(c, aH, bH);
    mmabf(c, aH, bL);
    mmabf(c, aL, bH);
}
__device__ __forceinline__ void ldsm_x4(uint32_t* r, uint32_t a) {
    asm volatile("ldmatrix.sync.aligned.m8n8.x4.shared.b16 {%0,%1,%2,%3}, [%4];"
                 : "=r"(r[0]), "=r"(r[1]), "=r"(r[2]), "=r"(r[3]) : "r"(a));
}
__device__ __forceinline__ void ldsm_x2(uint32_t* r, uint32_t a) {
    asm volatile("ldmatrix.sync.aligned.m8n8.x2.shared.b16 {%0,%1}, [%2];"
                 : "=r"(r[0]), "=r"(r[1]) : "r"(a));
}
__device__ __forceinline__ uint32_t smem_u32(const void* p) {
    uint32_t a;
    asm("{ .reg .u64 t; cvta.to.shared.u64 t, %1; cvt.u32.u64 %0, t; }"
        : "=r"(a) : "l"(p));
    return a;
}
__device__ __forceinline__ void cpa16(uint32_t sa, const void* g) {
    asm volatile("cp.async.cg.shared.global [%0], [%1], 16;"
                 :: "r"(sa), "l"(g) : "memory");
}
__device__ __forceinline__ void cpa16z(uint32_t sa, const void* g, bool valid) {
    int sz = valid ? 16 : 0;
    asm volatile("cp.async.cg.shared.global [%0], [%1], 16, %2;"
                 :: "r"(sa), "l"(g), "r"(sz) : "memory");
}
#define CP_COMMIT() asm volatile("cp.async.commit_group;" ::: "memory")
#define CP_WAIT1()  asm volatile("cp.async.wait_group 1;"  ::: "memory")
#define CP_WAIT0()  asm volatile("cp.async.wait_group 0;"  ::: "memory")

// ============================================================================
// prep_kernel: ONE launch covering all independent preprocessing:
//   [0,8192)        repack x        -> xH/xL
//   [8192,16384)    repack ctx      -> cH/cL
//   [16384,16448)   repack Wq (grid 8x8)
//   [16448,16512)   repack Wk
//   [16512,16576)   repack Wv
//   [16576,16640)   repack Wo (grid 4x16)
//   [16640,16644)   compact_mask (1 block per batch)
// ============================================================================
#define PREP_C0  8192
#define PREP_WQ  16384
#define PREP_WK  16448
#define PREP_WV  16512
#define PREP_WO  16576
#define PREP_CM  16640
#define PREP_NB  16644

__device__ __forceinline__ void repack_a_body(const float* __restrict__ A,
                                              uint32_t* __restrict__ H,
                                              uint32_t* __restrict__ L,
                                              int blk, int tid)
{
    int i = blk * 256 + tid;
    float4 a = ((const float4*)A)[i];
    uint32_t h0, l0, h1, l1;
    split_pair(a.x, a.y, h0, l0);
    split_pair(a.z, a.w, h1, l1);
    H[2 * i] = h0; H[2 * i + 1] = h1;
    L[2 * i] = l0; L[2 * i + 1] = l1;
}

__device__ __forceinline__ void repack_w_body(const float* __restrict__ W,
                                              uint32_t* __restrict__ H,
                                              uint32_t* __restrict__ L,
                                              int K, int N, int k0, int n0,
                                              float SM[128][68], int tid)
{
    #pragma unroll
    for (int j = 0; j < 8; j++) {
        int idx = tid + j * 256;
        int r = idx >> 4, c4 = (idx & 15) * 4;
        *(float4*)&SM[r][c4] = *(const float4*)(W + (size_t)(k0 + r) * N + n0 + c4);
    }
    __syncthreads();
    #pragma unroll
    for (int j = 0; j < 16; j++) {
        int idx = tid + j * 256;
        int n = idx >> 6, kp = idx & 63;
        uint32_t h, l;
        split_pair(SM[2 * kp][n], SM[2 * kp + 1][n], h, l);
        size_t d = (size_t)(n0 + n) * (K / 2) + k0 / 2 + kp;
        H[d] = h; L[d] = l;
    }
}

__global__ __launch_bounds__(256)
void prep_kernel(const float* __restrict__ x, const float* __restrict__ ctx,
                 const int* __restrict__ mask,
                 const float* __restrict__ Wq, const float* __restrict__ Wk,
                 const float* __restrict__ Wv, const float* __restrict__ Wo,
                 uint32_t* xH, uint32_t* xL, uint32_t* cH, uint32_t* cL,
                 uint32_t* WqH, uint32_t* WqL, uint32_t* WkH, uint32_t* WkL,
                 uint32_t* WvH, uint32_t* WvL, uint32_t* WoH, uint32_t* WoL,
                 int* __restrict__ idxOut, int* __restrict__ cntOut)
{
    __shared__ float SM[128][68];
    const int bid = blockIdx.x, tid = threadIdx.x;

    if (bid < PREP_C0) {
        repack_a_body(x, xH, xL, bid, tid);
    } else if (bid < PREP_WQ) {
        repack_a_body(ctx, cH, cL, bid - PREP_C0, tid);
    } else if (bid < PREP_WK) {
        int b = bid - PREP_WQ;
        repack_w_body(Wq, WqH, WqL, 1024, 512, (b & 7) * 128, (b >> 3) * 64, SM, tid);
    } else if (bid < PREP_WV) {
        int b = bid - PREP_WK;
        repack_w_body(Wk, WkH, WkL, 1024, 512, (b & 7) * 128, (b >> 3) * 64, SM, tid);
    } else if (bid < PREP_WO) {
        int b = bid - PREP_WV;
        repack_w_body(Wv, WvH, WvL, 1024, 512, (b & 7) * 128, (b >> 3) * 64, SM, tid);
    } else if (bid < PREP_CM) {
        int b = bid - PREP_WO;
        repack_w_body(Wo, WoH, WoL, 512, 1024, (b & 3) * 128, (b >> 2) * 64, SM, tid);
    } else {
        // compact_mask body (1 block per batch)
        int* ws = (int*)&SM[0][0];
        const int b = bid - PREP_CM;
        const int lane = tid & 31, w = tid >> 5;
        const int* mb = mask + b * MK;
        int loc[8], c = 0;
        #pragma unroll
        for (int j = 0; j < 8; j++) {
            loc[j] = (mb[tid * 8 + j] != 0);
            c += loc[j];
        }
        int pre = c;
        #pragma unroll
        for (int off = 1; off < 32; off <<= 1) {
            int v = __shfl_up_sync(0xffffffffu, pre, off);
            if (lane >= off) pre += v;
        }
        if (lane == 31) ws[w] = pre;
        __syncthreads();
        if (tid == 0) {
            int s = 0;
            #pragma unroll
            for (int i = 0; i < 8; i++) { int t2 = ws[i]; ws[i] = s; s += t2; }
            cntOut[b] = s;
        }
        __syncthreads();
        int start = ws[w] + pre - c;
        #pragma unroll
        for (int j = 0; j < 8; j++)
            if (loc[j]) idxOut[b * MK + start++] = tid * 8 + j;
    }
}

// ============================================================================
// repack_v (key gather/compaction): fp32 V [B*2048][512] -> per-(b,h)
// transposed packed [64 d][1024 keypair], keys reordered by idx, zero-filled
// past cnt. grid (2048/128, 32)
// ============================================================================
__global__ __launch_bounds__(256)
void repack_v(const float* __restrict__ V, uint32_t* __restrict__ H,
              uint32_t* __restrict__ L, const int* __restrict__ idx,
              const int* __restrict__ cnt)
{
    __shared__ float SM[128][68];
    const int tid = threadIdx.x;
    const int bh = blockIdx.y, b = bh >> 3, h = bh & 7;
    const int k0 = blockIdx.x * 128;
    const int cntb = cnt[b];
    #pragma unroll
    for (int j = 0; j < 8; j++) {
        int i2 = tid + j * 256;
        int r = i2 >> 4, c4 = (i2 & 15) * 4;
        float4 v = make_float4(0.f, 0.f, 0.f, 0.f);
        const int tok_i = k0 + r;
        if (tok_i < cntb) {
            const int tok = idx[b * MK + tok_i];
            v = *(const float4*)(V + (size_t)(b * 2048 + tok) * 512 + h * 64 + c4);
        }
        *(float4*)&SM[r][c4] = v;
    }
    __syncthreads();
    #pragma unroll
    for (int j = 0; j < 16; j++) {
        int i2 = tid + j * 256;
        int d = i2 >> 6, kp = i2 & 63;
        uint32_t hh, ll;
        split_pair(SM[2 * kp][d], SM[2 * kp + 1][d], hh, ll);
        size_t dst = ((size_t)bh * 64 + d) * 1024 + k0 / 2 + kp;
        H[dst] = hh; L[dst] = ll;
    }
}

// ============================================================================
// Shared GEMM mainloop pieces (BM=128, BN=128, BK=32; 256 thr, warp 32x64)
// ============================================================================
#define GB 10240   // words per stage buffer

struct GemmCtx {
    uint32_t smb;
    int tid, lane, warp, wm, wn, g, t;
    int arow_sel, acol_sel, brow_sel, bcol_sel;
    int srow, sseg;
};
__device__ __forceinline__ void gemm_init(GemmCtx& c) {
    c.tid = threadIdx.x;
    c.lane = c.tid & 31; c.warp = c.tid >> 5;
    c.wm = c.warp & 3; c.wn = c.warp >> 2;
    c.g = c.lane >> 2; c.t = c.lane & 3;
    c.arow_sel = (c.lane & 7) + (c.lane & 8);
    c.acol_sel = (c.lane & 16) ? 4 : 0;
    c.brow_sel = c.lane & 7;
    c.bcol_sel = (c.lane & 8) ? 4 : 0;
    c.srow = c.tid >> 2; c.sseg = c.tid & 3;
}
__device__ __forceinline__ void gemm_stage(const GemmCtx& c,
                                           const uint32_t* AH, const uint32_t* AL,
                                           const uint32_t* BH, const uint32_t* BL,
                                           int m0, int n0, int Kw,
                                           int buf, int k0) {
    const int base = buf * GB;
    #pragma unroll
    for (int j = 0; j < 2; j++) {
        const int row = c.srow + j * 64;
        const uint32_t sa = c.smb + (uint32_t)((base + row * 20 + c.sseg * 4) * 4);
        const size_t ga = (size_t)(m0 + row) * Kw + (k0 >> 1) + c.sseg * 4;
        cpa16(sa, AH + ga);
        cpa16(sa + 2560 * 4, AL + ga);
        const size_t gb = (size_t)(n0 + row) * Kw + (k0 >> 1) + c.sseg * 4;
        cpa16(sa + 5120 * 4, BH + gb);
        cpa16(sa + 7680 * 4, BL + gb);
    }
}
__device__ __forceinline__ void gemm_mainloop(const GemmCtx& c,
                                              const uint32_t* AH, const uint32_t* AL,
                                              const uint32_t* BH, const uint32_t* BL,
                                              int m0, int n0, int K,
                                              float acc[2][8][4]) {
    const int Kw = K >> 1;
    #pragma unroll
    for (int mt = 0; mt < 2; mt++)
        #pragma unroll
        for (int nt = 0; nt < 8; nt++)
            #pragma unroll
            for (int i = 0; i < 4; i++) acc[mt][nt][i] = 0.f;

    gemm_stage(c, AH, AL, BH, BL, m0, n0, Kw, 0, 0);
    CP_COMMIT();

    int buf = 0;
    for (int k0 = 0; k0 < K; k0 += 32) {
        if (k0 + 32 < K) {
            gemm_stage(c, AH, AL, BH, BL, m0, n0, Kw, buf ^ 1, k0 + 32);
            CP_COMMIT();
            CP_WAIT1();
        } else {
            CP_WAIT0();
        }
        __syncthreads();

        const int base = buf * GB;
        #pragma unroll
        for (int s = 0; s < 2; s++) {
            uint32_t aH[2][4], aL[2][4];
            #pragma unroll
            for (int mt = 0; mt < 2; mt++) {
                const uint32_t aoff = c.smb +
                    (uint32_t)((base + (c.wm * 32 + mt * 16 + c.arow_sel) * 20 +
                                s * 8 + c.acol_sel) * 4);
                ldsm_x4(aH[mt], aoff);
                ldsm_x4(aL[mt], aoff + 2560 * 4);
            }
            #pragma unroll
            for (int nt = 0; nt < 8; nt++) {
                const uint32_t boff = c.smb +
                    (uint32_t)((base + (c.wn * 64 + nt * 8 + c.brow_sel) * 20 +
                                s * 8 + c.bcol_sel) * 4);
                uint32_t bH[2], bL[2];
                ldsm_x2(bH, boff + 5120 * 4);
                ldsm_x2(bL, boff + 7680 * 4);
                mmabf_x3(acc[0][nt], aH[0], aL[0], bH, bL);
                mmabf_x3(acc[1][nt], aH[1], aL[1], bH, bL);
            }
        }
        __syncthreads();
        buf ^= 1;
    }
}

// ============================================================================
// proj_kernel: ONE launch for all 3 projections (blockIdx.z = 0:Q, 1:K, 2:V).
// Q/K epilogue -> packed [b,h][tok][dpair]; V epilogue -> fp32 Vf.
// grid (512/128, 8192/128, 3)
// ============================================================================
__global__ __launch_bounds__(256, 2)
void proj_kernel(const uint32_t* __restrict__ xH, const uint32_t* __restrict__ xL,
                 const uint32_t* __restrict__ cH, const uint32_t* __restrict__ cL,
                 const uint32_t* __restrict__ WqH, const uint32_t* __restrict__ WqL,
                 const uint32_t* __restrict__ WkH, const uint32_t* __restrict__ WkL,
                 const uint32_t* __restrict__ WvH, const uint32_t* __restrict__ WvL,
                 uint32_t* __restrict__ QH, uint32_t* __restrict__ QL,
                 uint32_t* __restrict__ KH, uint32_t* __restrict__ KL,
                 float* __restrict__ Vf)
{
    extern __shared__ uint32_t gs[];
    GemmCtx c;
    gemm_init(c);
    c.smb = smem_u32(gs);

    const int z = blockIdx.z;
    const int m0 = blockIdx.y * 128, n0 = blockIdx.x * 128;
    const uint32_t *AH, *AL, *BH, *BL;
    if (z == 0)      { AH = xH; AL = xL; BH = WqH; BL = WqL; }
    else if (z == 1) { AH = cH; AL = cL; BH = WkH; BL = WkL; }
    else             { AH = cH; AL = cL; BH = WvH; BL = WvL; }

    float acc[2][8][4];
    gemm_mainloop(c, AH, AL, BH, BL, m0, n0, 1024, acc);

    if (z == 2) {
        // fp32 V out
        #pragma unroll
        for (int mt = 0; mt < 2; mt++) {
            const int r0 = m0 + c.wm * 32 + mt * 16 + c.g;
            #pragma unroll
            for (int nt = 0; nt < 8; nt++) {
                const int c0 = n0 + c.wn * 64 + nt * 8 + c.t * 2;
                *(float2*)(Vf + (size_t)r0 * 512 + c0) =
                    make_float2(acc[mt][nt][0], acc[mt][nt][1]);
                *(float2*)(Vf + (size_t)(r0 + 8) * 512 + c0) =
                    make_float2(acc[mt][nt][2], acc[mt][nt][3]);
            }
        }
    } else {
        uint32_t* OH = (z == 0) ? QH : KH;
        uint32_t* OL = (z == 0) ? QL : KL;
        #pragma unroll
        for (int mt = 0; mt < 2; mt++) {
            const int r0 = m0 + c.wm * 32 + mt * 16 + c.g;
            const int b = r0 >> 11;
            #pragma unroll
            for (int nt = 0; nt < 8; nt++) {
                const int c0 = n0 + c.wn * 64 + nt * 8 + c.t * 2;
                const int h = c0 >> 6, w = (c0 & 63) >> 1;
                uint32_t hh, ll;
                split_pair(acc[mt][nt][0], acc[mt][nt][1], hh, ll);
                size_t d0 = ((size_t)(b * 8 + h) * 2048 + (r0 & 2047)) * 32 + w;
                OH[d0] = hh; OL[d0] = ll;
                split_pair(acc[mt][nt][2], acc[mt][nt][3], hh, ll);
                size_t d1 = d0 + 8 * 32;
                OH[d1] = hh; OL[d1] = ll;
            }
        }
    }
}

// ============================================================================
// out_gemm: out = O @ Wo + bo (packed operands), fp32 out.
// grid (1024/128, 8192/128)
// ============================================================================
__global__ __launch_bounds__(256, 2)
void out_gemm(const uint32_t* __restrict__ AH, const uint32_t* __restrict__ AL,
              const uint32_t* __restrict__ BH, const uint32_t* __restrict__ BL,
              float* __restrict__ C, const float* __restrict__ bias)
{
    extern __shared__ uint32_t gs[];
    GemmCtx c;
    gemm_init(c);
    c.smb = smem_u32(gs);
    const int m0 = blockIdx.y * 128, n0 = blockIdx.x * 128;

    float acc[2][8][4];
    gemm_mainloop(c, AH, AL, BH, BL, m0, n0, 512, acc);

    #pragma unroll
    for (int mt = 0; mt < 2; mt++) {
        const int r0 = m0 + c.wm * 32 + mt * 16 + c.g;
        #pragma unroll
        for (int nt = 0; nt < 8; nt++) {
            const int c0 = n0 + c.wn * 64 + nt * 8 + c.t * 2;
            float b0v = bias[c0], b1v = bias[c0 + 1];
            *(float2*)(C + (size_t)r0 * 1024 + c0) =
                make_float2(acc[mt][nt][0] + b0v, acc[mt][nt][1] + b1v);
            *(float2*)(C + (size_t)(r0 + 8) * 1024 + c0) =
                make_float2(acc[mt][nt][2] + b0v, acc[mt][nt][3] + b1v);
        }
    }
}

// ============================================================================
// flash_cp: bf16 x3, P in registers, cp.async double-buffered, compacted keys.
// ============================================================================
#define FL_KV    9216
#define FL_BUF   9216
#define FLASH_SMEM_BYTES ((FL_KV + 2 * FL_BUF) * 4)

__global__ __launch_bounds__(256, 2)
void flash_cp(const uint32_t* __restrict__ QHg, const uint32_t* __restrict__ QLg,
              const uint32_t* __restrict__ KHg, const uint32_t* __restrict__ KLg,
              const uint32_t* __restrict__ VHg, const uint32_t* __restrict__ VLg,
              const int* __restrict__ idx, const int* __restrict__ cnt,
              uint32_t* __restrict__ OH, uint32_t* __restrict__ OL)
{
    extern __shared__ uint32_t fsm[];
    const uint32_t smb = smem_u32(fsm);

    const int bh = blockIdx.y;
    const int b = bh >> 3, h = bh & 7;
    const int q0 = blockIdx.x * 128;

    const int tid = threadIdx.x;
    const int lane = tid & 31, warp = tid >> 5;
    const int g = lane >> 2, t = lane & 3;
    const int pr = warp * 16;

    const int arow_sel = (lane & 7) + (lane & 8);
    const int acol_sel = (lane & 16) ? 4 : 0;
    const int brow_sel = lane & 7;
    const int bcol_sel = (lane & 8) ? 4 : 0;

    const int cntb = cnt[b];
    const int Mp = (cntb + 63) & ~63;
    const int* gidx = idx + b * MK;

    auto stageKV = [&](int nb, int kt2) {
        const int base = FL_KV + nb * FL_BUF;
        #pragma unroll
        for (int j = 0; j < 2; j++) {
            const int i2 = tid + j * 256;
            const int r = i2 >> 3, sg = i2 & 7;
            const int tok_i = kt2 + r;
            const bool valid = tok_i < cntb;
            const int tok = valid ? gidx[tok_i] : 0;
            const uint32_t sa = smb + (uint32_t)((base + r * 36 + sg * 4) * 4);
            const size_t gk = ((size_t)bh * 2048 + tok) * 32 + sg * 4;
            cpa16z(sa, KHg + gk, valid);
            cpa16z(sa + 2304 * 4, KLg + gk, valid);
            const size_t gv = ((size_t)bh * 64 + r) * 1024 + (kt2 >> 1) + sg * 4;
            cpa16(sa + 4608 * 4, VHg + gv);
            cpa16(sa + 6912 * 4, VLg + gv);
        }
    };

    // prologue: stage Q + tile 0
    #pragma unroll
    for (int j = 0; j < 4; j++) {
        const int i2 = tid + j * 256;
        const int row = i2 >> 3, seg = i2 & 7;
        const uint32_t sa = smb + (uint32_t)((row * 36 + seg * 4) * 4);
        const size_t gq = ((size_t)bh * 2048 + q0 + row) * 32 + seg * 4;
        cpa16(sa, QHg + gq);
        cpa16(sa + 4608 * 4, QLg + gq);
    }
    stageKV(0, 0);
    CP_COMMIT();

    float of[8][4];
    #pragma unroll
    for (int nt = 0; nt < 8; nt++)
        #pragma unroll
        for (int i = 0; i < 4; i++) of[nt][i] = 0.f;
    float mrow0 = -3.0e38f, mrow1 = -3.0e38f, lrow0 = 0.f, lrow1 = 0.f;
    const float scale = 0.125f;

    int buf = 0;
    for (int kt = 0; kt < Mp; kt += 64) {
        if (kt + 64 < Mp) {
            stageKV(buf ^ 1, kt + 64);
            CP_COMMIT();
            CP_WAIT1();
        } else {
            CP_WAIT0();
        }
        __syncthreads();

        const int base = FL_KV + buf * FL_BUF;
        const int limit = cntb - kt;

        // ---- S = Q K^T ----
        float sf[8][4];
        #pragma unroll
        for (int nt = 0; nt < 8; nt++)
            #pragma unroll
            for (int i = 0; i < 4; i++) sf[nt][i] = 0.f;

        #pragma unroll
        for (int s = 0; s < 4; s++) {
            uint32_t aH[4], aL[4];
            const uint32_t qoff = smb +
                (uint32_t)(((pr + arow_sel) * 36 + s * 8 + acol_sel) * 4);
            ldsm_x4(aH, qoff);
            ldsm_x4(aL, qoff + 4608 * 4);
            #pragma unroll
            for (int nt = 0; nt < 8; nt++) {
                const uint32_t koff = smb +
                    (uint32_t)((base + (nt * 8 + brow_sel) * 36 + s * 8 + bcol_sel) * 4);
                uint32_t bH[2], bL[2];
                ldsm_x2(bH, koff);
                ldsm_x2(bL, koff + 2304 * 4);
                mmabf_x3(sf[nt], aH, aL, bH, bL);
            }
        }

        // ---- scale + validity + online softmax ----
        float mx0 = -3.0e38f, mx1 = -3.0e38f;
        #pragma unroll
        for (int nt = 0; nt < 8; nt++) {
            const int c0 = nt * 8 + 2 * t;
            float mk0 = (c0     < limit) ? 0.f : -1.0e30f;
            float mk1 = (c0 + 1 < limit) ? 0.f : -1.0e30f;
            sf[nt][0] = sf[nt][0] * scale + mk0;
            sf[nt][1] = sf[nt][1] * scale + mk1;
            sf[nt][2] = sf[nt][2] * scale + mk0;
            sf[nt][3] = sf[nt][3] * scale + mk1;
            mx0 = fmaxf(mx0, fmaxf(sf[nt][0], sf[nt][1]));
            mx1 = fmaxf(mx1, fmaxf(sf[nt][2], sf[nt][3]));
        }
        mx0 = fmaxf(mx0, __shfl_xor_sync(0xffffffffu, mx0, 1));
        mx0 = fmaxf(mx0, __shfl_xor_sync(0xffffffffu, mx0, 2));
        mx1 = fmaxf(mx1, __shfl_xor_sync(0xffffffffu, mx1, 1));
        mx1 = fmaxf(mx1, __shfl_xor_sync(0xffffffffu, mx1, 2));

        const float mn0 = fmaxf(mrow0, mx0), mn1 = fmaxf(mrow1, mx1);
        const float corr0 = __expf(mrow0 - mn0), corr1 = __expf(mrow1 - mn1);
        float ls0 = 0.f, ls1 = 0.f;
        #pragma unroll
        for (int nt = 0; nt < 8; nt++) {
            sf[nt][0] = __expf(sf[nt][0] - mn0);
            sf[nt][1] = __expf(sf[nt][1] - mn0);
            sf[nt][2] = __expf(sf[nt][2] - mn1);
            sf[nt][3] = __expf(sf[nt][3] - mn1);
            ls0 += sf[nt][0] + sf[nt][1];
            ls1 += sf[nt][2] + sf[nt][3];
        }
        ls0 += __shfl_xor_sync(0xffffffffu, ls0, 1);
        ls0 += __shfl_xor_sync(0xffffffffu, ls0, 2);
        ls1 += __shfl_xor_sync(0xffffffffu, ls1, 1);
        ls1 += __shfl_xor_sync(0xffffffffu, ls1, 2);

        lrow0 = lrow0 * corr0 + ls0; mrow0 = mn0;
        lrow1 = lrow1 * corr1 + ls1; mrow1 = mn1;

        #pragma unroll
        for (int nt = 0; nt < 8; nt++) {
            of[nt][0] *= corr0; of[nt][1] *= corr0;
            of[nt][2] *= corr1; of[nt][3] *= corr1;
        }

        // ---- O += P @ V ----
        #pragma unroll
        for (int u = 0; u < 4; u++) {
            uint32_t pH[4], pL[4];
            split_pair(sf[2 * u][0],     sf[2 * u][1],     pH[0], pL[0]);
            split_pair(sf[2 * u][2],     sf[2 * u][3],     pH[1], pL[1]);
            split_pair(sf[2 * u + 1][0], sf[2 * u + 1][1], pH[2], pL[2]);
            split_pair(sf[2 * u + 1][2], sf[2 * u + 1][3], pH[3], pL[3]);
            #pragma unroll
            for (int nt = 0; nt < 8; nt++) {
                const uint32_t voff = smb +
                    (uint32_t)((base + (nt * 8 + brow_sel) * 36 + u * 8 + bcol_sel) * 4);
                uint32_t bH[2], bL[2];
                ldsm_x2(bH, voff + 4608 * 4);
                ldsm_x2(bL, voff + 6912 * 4);
                mmabf_x3(of[nt], pH, pL, bH, bL);
            }
        }
        __syncthreads();
        buf ^= 1;
    }

    // epilogue: packed hi/lo O out ([tok][INNER/2 words])
    const float inv0 = 1.f / lrow0, inv1 = 1.f / lrow1;
    const int qa = q0 + pr + g;
    const size_t ro0 = ((size_t)(b * 2048 + qa)) * 256;
    const size_t ro1 = ro0 + 8 * 256;
    #pragma unroll
    for (int nt = 0; nt < 8; nt++) {
        const int w = h * 32 + nt * 4 + t;
        uint32_t hh, ll;
        split_pair(of[nt][0] * inv0, of[nt][1] * inv0, hh, ll);
        OH[ro0 + w] = hh; OL[ro0 + w] = ll;
        split_pair(of[nt][2] * inv1, of[nt][3] * inv1, hh, ll);
        OH[ro1 + w] = hh; OL[ro1 + w] = ll;
    }
}

// ----------------------------------------------------------------------------
// kernel_launch — 5 launches total.
// Inputs: 0=x, 1=context, 2=mask (int32), 3=Wq, 4=Wk, 5=Wv, 6=Wo, 7=bo
// ----------------------------------------------------------------------------
extern "C" void kernel_launch(void* const* d_in, const int* in_sizes, int n_in,
                              void* d_out, int out_size)
{
    const float* x    = (const float*)d_in[0];
    const float* ctx  = (const float*)d_in[1];
    const int*   mask = (const int*)d_in[2];
    const float* Wq   = (const float*)d_in[3];
    const float* Wk   = (const float*)d_in[4];
    const float* Wv   = (const float*)d_in[5];
    const float* Wo   = (const float*)d_in[6];
    const float* bo   = (const float*)d_in[7];
    float* out = (float*)d_out;

    uint32_t *xH, *xL, *cH, *cL, *WqH, *WqL, *WkH, *WkL, *WvH, *WvL, *WoH, *WoL;
    uint32_t *QH, *QL, *KH, *KL, *VtH, *VtL, *OH2, *OL2;
    float *Vf;
    int *pidx, *pcnt;
    cudaGetSymbolAddress((void**)&xH, g_xH);   cudaGetSymbolAddress((void**)&xL, g_xL);
    cudaGetSymbolAddress((void**)&cH, g_cH);   cudaGetSymbolAddress((void**)&cL, g_cL);
    cudaGetSymbolAddress((void**)&WqH, g_WqH); cudaGetSymbolAddress((void**)&WqL, g_WqL);
    cudaGetSymbolAddress((void**)&WkH, g_WkH); cudaGetSymbolAddress((void**)&WkL, g_WkL);
    cudaGetSymbolAddress((void**)&WvH, g_WvH); cudaGetSymbolAddress((void**)&WvL, g_WvL);
    cudaGetSymbolAddress((void**)&WoH, g_WoH); cudaGetSymbolAddress((void**)&WoL, g_WoL);
    cudaGetSymbolAddress((void**)&QH, g_QH);   cudaGetSymbolAddress((void**)&QL, g_QL);
    cudaGetSymbolAddress((void**)&KH, g_KH);   cudaGetSymbolAddress((void**)&KL, g_KL);
    cudaGetSymbolAddress((void**)&VtH, g_VtH); cudaGetSymbolAddress((void**)&VtL, g_VtL);
    cudaGetSymbolAddress((void**)&OH2, g_OH2); cudaGetSymbolAddress((void**)&OL2, g_OL2);
    cudaGetSymbolAddress((void**)&Vf, g_Vf);
    cudaGetSymbolAddress((void**)&pidx, g_idx);
    cudaGetSymbolAddress((void**)&pcnt, g_cnt);

    cudaFuncSetAttribute(proj_kernel, cudaFuncAttributeMaxDynamicSharedMemorySize,
                         2 * GB * 4);
    cudaFuncSetAttribute(out_gemm, cudaFuncAttributeMaxDynamicSharedMemorySize,
                         2 * GB * 4);
    cudaFuncSetAttribute(flash_cp, cudaFuncAttributeMaxDynamicSharedMemorySize,
                         FLASH_SMEM_BYTES);

    // 1) all preprocessing in one launch
    prep_kernel<<<PREP_NB, 256>>>(x, ctx, mask, Wq, Wk, Wv, Wo,
                                  xH, xL, cH, cL,
                                  WqH, WqL, WkH, WkL, WvH, WvL, WoH, WoL,
                                  pidx, pcnt);

    // 2) all three projections in one launch
    {
        dim3 gp(512 / 128, 8192 / 128, 3);
        proj_kernel<<<gp, 256, 2 * GB * 4>>>(xH, xL, cH, cL,
                                             WqH, WqL, WkH, WkL, WvH, WvL,
                                             QH, QL, KH, KL, Vf);
    }

    // 3) V transpose + gather
    repack_v<<<dim3(16, 32), 256>>>(Vf, VtH, VtL, pidx, pcnt);

    // 4) flash attention over compacted keys
    {
        dim3 grid(NQ / 128, BSZ * HEADS);
        flash_cp<<<grid, 256, FLASH_SMEM_BYTES>>>(QH, QL, KH, KL, VtH, VtL,
                                                  pidx, pcnt, OH2, OL2);
    }
    // 5) out = O @ Wo + bo
    {
        dim3 go(1024 / 128, 8192 / 128);
        out_gemm<<<go, 256, 2 * GB * 4>>>(OH2, OL2, WoH, WoL, out, bo);
    }
}